// round 3
// baseline (speedup 1.0000x reference)
#include <cuda_runtime.h>
#include <cuda_bf16.h>
#include <math.h>

// ---------------------------------------------------------------------------
// ConvCrossAttention: x1,x2 [16,256,32,32] -> out [2,16,256,32,32] f32
//   dwconv3x3+BN (q: stride1 -> 1024 pos, kv: stride2 -> 256 pos)
//   pointwise projections (GEMM), 8-head cross attention (d=64), out proj.
// ---------------------------------------------------------------------------

// Scratch (device globals; dynamic allocation is forbidden)
__device__ float g_yq [2*16*256*1024];   // dwconv out, q path   [s][b][c][p]
__device__ float g_ykv[2*16*256*256];    // dwconv out, kv path  [s][b][c][j]
__device__ float g_q  [2*16*8*1024*64];  // [s][b][h][p][d]
__device__ float g_k  [2*16*8*256*64];   // [s][b][h][j][d]
__device__ float g_v  [2*16*8*256*64];   // [s][b][h][j][d]
__device__ float g_o  [2*16*512*1024];   // attn out, [s][b][c][p] (c=h*64+d)

// ---------------------------------------------------------------------------
// Depthwise 3x3 conv + folded BN. dst_kv selects g_ykv vs g_yq; off is the
// stream offset in elements.
// ---------------------------------------------------------------------------
__global__ void dwconv_kernel(const float* __restrict__ x, const float* __restrict__ dw,
                              const float* __restrict__ gam, const float* __restrict__ bet,
                              const float* __restrict__ rm, const float* __restrict__ rv,
                              int dst_kv, int off, int stride, int OH)
{
    int idx = blockIdx.x * blockDim.x + threadIdx.x;
    int total = 16 * 256 * OH * OH;
    if (idx >= total) return;
    int ox = idx % OH; int t = idx / OH;
    int oy = t % OH;   t /= OH;
    int c = t & 255;   int b = t >> 8;

    const float* xp = x + ((b << 8) | c) * 1024;
    const float* w  = dw + c * 9;
    int iy0 = oy * stride - 1, ix0 = ox * stride - 1;
    float acc = 0.f;
#pragma unroll
    for (int ky = 0; ky < 3; ky++) {
        int iy = iy0 + ky;
        if ((unsigned)iy < 32u) {
#pragma unroll
            for (int kx = 0; kx < 3; kx++) {
                int ix = ix0 + kx;
                if ((unsigned)ix < 32u) acc += xp[iy * 32 + ix] * w[ky * 3 + kx];
            }
        }
    }
    float inv = gam[c] * rsqrtf(rv[c] + 1e-5f);
    float r = acc * inv + (bet[c] - rm[c] * inv);
    float* y = dst_kv ? g_ykv : g_yq;
    y[off + idx] = r;
}

// ---------------------------------------------------------------------------
// Batched tiled GEMM: C[z] = A(stream) [M,K] @ B[z] [K,N], z = s*16+b.
// mode 0: B=g_yq,  out -> g_q head scatter  [((z*8+h)*N + n)*64 + d], m=h*64+d
// mode 1: B=g_ykv, out -> g_k (m<512) / g_v (m>=512), same scatter
// mode 2: B=g_o,   out -> Ob row-major + bias
// Block 64x64, BK=16, 256 threads, 4x4 microtile.
// ---------------------------------------------------------------------------
#define GM 64
#define GN 64
#define GK 16

__global__ void gemm_kernel(const float* __restrict__ A0, const float* __restrict__ A1,
                            int M, int N, int K, int mode,
                            float* __restrict__ Ob,
                            const float* __restrict__ bias0, const float* __restrict__ bias1)
{
    __shared__ float As[GK][GM];
    __shared__ float Bs[GK][GN];

    int z = blockIdx.z;
    int s = z >> 4;
    const float* A = s ? A1 : A0;
    const float* B;
    long bStride;
    if (mode == 0)      { B = g_yq;  bStride = 256L * 1024; }
    else if (mode == 1) { B = g_ykv; bStride = 256L * 256;  }
    else                { B = g_o;   bStride = 512L * 1024; }
    B += (long)z * bStride;

    int m0 = blockIdx.y * GM, n0 = blockIdx.x * GN;
    int tx = threadIdx.x, ty = threadIdx.y;
    int tid = ty * 16 + tx;

    float acc[4][4] = {};
    int ar = tid >> 2, akq = (tid & 3) * 4;    // A: 64 rows x 16 k
    int bk = tid >> 4, bnq = (tid & 15) * 4;   // B: 16 k x 64 n

    for (int k0 = 0; k0 < K; k0 += GK) {
        float4 av = *(const float4*)&A[(long)(m0 + ar) * K + k0 + akq];
        As[akq + 0][ar] = av.x; As[akq + 1][ar] = av.y;
        As[akq + 2][ar] = av.z; As[akq + 3][ar] = av.w;
        *(float4*)&Bs[bk][bnq] = *(const float4*)&B[(long)(k0 + bk) * N + n0 + bnq];
        __syncthreads();
#pragma unroll
        for (int kk = 0; kk < GK; kk++) {
            float4 a4 = *(const float4*)&As[kk][ty * 4];
            float4 b4 = *(const float4*)&Bs[kk][tx * 4];
            float af[4] = {a4.x, a4.y, a4.z, a4.w};
            float bf[4] = {b4.x, b4.y, b4.z, b4.w};
#pragma unroll
            for (int i = 0; i < 4; i++)
#pragma unroll
                for (int j = 0; j < 4; j++)
                    acc[i][j] += af[i] * bf[j];
        }
        __syncthreads();
    }

    if (mode == 2) {
        const float* bias = s ? bias1 : bias0;
#pragma unroll
        for (int i = 0; i < 4; i++) {
            int m = m0 + ty * 4 + i;
            float bv = bias[m];
#pragma unroll
            for (int j = 0; j < 4; j++) {
                int n = n0 + tx * 4 + j;
                Ob[((long)z * M + m) * N + n] = acc[i][j] + bv;
            }
        }
    } else {
#pragma unroll
        for (int i = 0; i < 4; i++) {
            int m = m0 + ty * 4 + i;
            float* O;
            int mm = m;
            if (mode == 0) O = g_q;
            else if (m < 512) O = g_k;
            else { O = g_v; mm = m - 512; }
            long base = ((long)(z * 8 + (mm >> 6))) * N * 64 + (mm & 63);
#pragma unroll
            for (int j = 0; j < 4; j++) {
                int n = n0 + tx * 4 + j;
                O[base + (long)n * 64] = acc[i][j];
            }
        }
    }
}

// ---------------------------------------------------------------------------
// Cross attention: o[s] = softmax(q[s] @ k[1-s]^T * 0.125) @ v[1-s]
// One block per (s,b,h): 256 blocks, 256 threads.
// K,V (256x64) resident in smem, rows padded to 65 floats (conflict-free).
// Each warp handles 4 q-rows per pass. Softmax scale folded into Q staging.
// ---------------------------------------------------------------------------
#define ATT_SMEM_FLOATS (256*65*2 + 8*4*256 + 8*4*64)
#define ATT_SMEM_BYTES  (ATT_SMEM_FLOATS * 4)

__global__ void attn_kernel()
{
    extern __shared__ float sm[];
    float* Ks = sm;                  // 256 * 65
    float* Vs = Ks + 256 * 65;       // 256 * 65
    float* P  = Vs + 256 * 65;       // 8 warps * 4 rows * 256
    float* Qs = P + 8 * 4 * 256;     // 8 warps * 4 rows * 64

    int idx = blockIdx.x;            // s*128 + b*8 + h
    int s  = idx >> 7;
    int bh = idx & 127;
    int h  = bh & 7;
    const float* qp = g_q + (long)(s * 128 + bh) * 1024 * 64;
    const float* kp = g_k + (long)((1 - s) * 128 + bh) * 256 * 64;
    const float* vp = g_v + (long)((1 - s) * 128 + bh) * 256 * 64;
    float* op = g_o + (long)(s * 16 + (bh >> 3)) * 512 * 1024;

    int tid = threadIdx.x, wid = tid >> 5, lane = tid & 31;

    for (int i = tid; i < 4096; i += 256) {
        int j = i >> 4, dq = (i & 15) * 4;
        float4 kt = *(const float4*)&kp[j * 64 + dq];
        float4 vt = *(const float4*)&vp[j * 64 + dq];
        float* kd = &Ks[j * 65 + dq];
        kd[0] = kt.x; kd[1] = kt.y; kd[2] = kt.z; kd[3] = kt.w;
        float* vd = &Vs[j * 65 + dq];
        vd[0] = vt.x; vd[1] = vt.y; vd[2] = vt.z; vd[3] = vt.w;
    }
    __syncthreads();

    float* Pw = P + wid * 4 * 256;
    float* Qw = Qs + wid * 4 * 64;
    const float scale = 0.125f;  // 64^-0.5, folded into Q

    for (int r0 = wid * 4; r0 < 1024; r0 += 32) {
        for (int t2 = lane; t2 < 64; t2 += 32) {
            int r = t2 >> 4, dq = (t2 & 15) * 4;
            float4 qv = *(const float4*)&qp[(long)(r0 + r) * 64 + dq];
            qv.x *= scale; qv.y *= scale; qv.z *= scale; qv.w *= scale;
            *(float4*)&Qw[r * 64 + dq] = qv;
        }
        __syncwarp();

        float dot[4][8];
#pragma unroll
        for (int r = 0; r < 4; r++)
#pragma unroll
            for (int t = 0; t < 8; t++) dot[r][t] = 0.f;

#pragma unroll 4
        for (int d = 0; d < 64; d++) {
            float q0 = Qw[d], q1 = Qw[64 + d], q2 = Qw[128 + d], q3 = Qw[192 + d];
#pragma unroll
            for (int t = 0; t < 8; t++) {
                float kk = Ks[(lane + 32 * t) * 65 + d];
                dot[0][t] += q0 * kk;
                dot[1][t] += q1 * kk;
                dot[2][t] += q2 * kk;
                dot[3][t] += q3 * kk;
            }
        }

#pragma unroll
        for (int r = 0; r < 4; r++) {
            float mx = dot[r][0];
#pragma unroll
            for (int t = 1; t < 8; t++) mx = fmaxf(mx, dot[r][t]);
#pragma unroll
            for (int off = 16; off; off >>= 1)
                mx = fmaxf(mx, __shfl_xor_sync(0xffffffffu, mx, off));
            float sum = 0.f;
#pragma unroll
            for (int t = 0; t < 8; t++) {
                float e = __expf(dot[r][t] - mx);
                dot[r][t] = e;
                sum += e;
            }
#pragma unroll
            for (int off = 16; off; off >>= 1)
                sum += __shfl_xor_sync(0xffffffffu, sum, off);
            float inv = 1.f / sum;
#pragma unroll
            for (int t = 0; t < 8; t++)
                Pw[r * 256 + lane + 32 * t] = dot[r][t] * inv;
        }
        __syncwarp();

        float acc[4][2] = {};
        for (int j = 0; j < 256; j++) {
            float v0 = Vs[j * 65 + lane], v1 = Vs[j * 65 + lane + 32];
            float p0 = Pw[j], p1 = Pw[256 + j], p2 = Pw[512 + j], p3 = Pw[768 + j];
            acc[0][0] += p0 * v0; acc[0][1] += p0 * v1;
            acc[1][0] += p1 * v0; acc[1][1] += p1 * v1;
            acc[2][0] += p2 * v0; acc[2][1] += p2 * v1;
            acc[3][0] += p3 * v0; acc[3][1] += p3 * v1;
        }
        long ob = (long)(h * 64 + lane) * 1024;
#pragma unroll
        for (int r = 0; r < 4; r++) {
            op[ob + r0 + r]             = acc[r][0];
            op[ob + 32 * 1024 + r0 + r] = acc[r][1];
        }
        __syncwarp();
    }
}

// ---------------------------------------------------------------------------
// Orchestration. Input order:
// 0 x1, 1 x2, 2..7 q1(dw,g,b,rm,rv,pw), 8..13 kv1, 14..19 q2, 20..25 kv2,
// 26 out1_w, 27 out1_b, 28 out2_w, 29 out2_b
// ---------------------------------------------------------------------------
extern "C" void kernel_launch(void* const* d_in, const int* in_sizes, int n_in,
                              void* d_out, int out_size)
{
    (void)in_sizes; (void)n_in; (void)out_size;
    #define F(i) ((const float*)d_in[i])

    int tot1 = 16 * 256 * 1024;
    int tot2 = 16 * 256 * 256;
    dwconv_kernel<<<(tot1 + 255) / 256, 256>>>(F(0), F(2),  F(3),  F(4),  F(5),  F(6),  0, 0,    1, 32);
    dwconv_kernel<<<(tot1 + 255) / 256, 256>>>(F(1), F(14), F(15), F(16), F(17), F(18), 0, tot1, 1, 32);
    dwconv_kernel<<<(tot2 + 255) / 256, 256>>>(F(0), F(8),  F(9),  F(10), F(11), F(12), 1, 0,    2, 16);
    dwconv_kernel<<<(tot2 + 255) / 256, 256>>>(F(1), F(20), F(21), F(22), F(23), F(24), 1, tot2, 2, 16);

    dim3 thr(16, 16);
    // q projection:  [512,1024] = Wq[512,256] @ Yq[256,1024]
    gemm_kernel<<<dim3(1024 / GN, 512 / GM, 32), thr>>>(
        F(7), F(19), 512, 1024, 256, 0, nullptr, nullptr, nullptr);
    // kv projection: [1024,256] = Wkv[1024,256] @ Ykv[256,256]
    gemm_kernel<<<dim3(256 / GN, 1024 / GM, 32), thr>>>(
        F(13), F(25), 1024, 256, 256, 1, nullptr, nullptr, nullptr);

    cudaFuncSetAttribute(attn_kernel, cudaFuncAttributeMaxDynamicSharedMemorySize, ATT_SMEM_BYTES);
    attn_kernel<<<256, 256, ATT_SMEM_BYTES>>>();

    // out projection: [256,1024] = Wout[256,512] @ O[512,1024] + bias
    gemm_kernel<<<dim3(1024 / GN, 256 / GM, 32), thr>>>(
        F(26), F(28), 256, 1024, 512, 2, (float*)d_out, F(27), F(29));

    #undef F
}

// round 5
// speedup vs baseline: 1.1529x; 1.1529x over previous
#include <cuda_runtime.h>
#include <cuda_bf16.h>
#include <stdint.h>
#include <math.h>

// ---------------------------------------------------------------------------
// ConvCrossAttention on sm_100a.
// GEMMs run on tensor cores via mma.sync bf16 with 3xBF16 split (hi/lo)
// for fp32-class accuracy. Attention stays fp32 (this round).
// ---------------------------------------------------------------------------

// Scratch (device globals; dynamic allocation is forbidden)
__device__ __nv_bfloat16 g_yq_hi [2*16*256*1024];
__device__ __nv_bfloat16 g_yq_lo [2*16*256*1024];
__device__ __nv_bfloat16 g_ykv_hi[2*16*256*256];
__device__ __nv_bfloat16 g_ykv_lo[2*16*256*256];
__device__ float g_q[2*16*8*1024*64];   // [s][b][h][p][d]
__device__ float g_k[2*16*8*256*64];
__device__ float g_v[2*16*8*256*64];
__device__ __nv_bfloat16 g_o_hi[2*16*512*1024];   // attn out [s][b][c][p]
__device__ __nv_bfloat16 g_o_lo[2*16*512*1024];
__device__ __nv_bfloat16 g_wq_hi [2*512*256],  g_wq_lo [2*512*256];
__device__ __nv_bfloat16 g_wkv_hi[2*1024*256], g_wkv_lo[2*1024*256];
__device__ __nv_bfloat16 g_wo_hi [2*256*512],  g_wo_lo [2*256*512];

__device__ __forceinline__ void split_store(float v, __nv_bfloat16* hi,
                                            __nv_bfloat16* lo, long i)
{
    __nv_bfloat16 h = __float2bfloat16(v);
    hi[i] = h;
    lo[i] = __float2bfloat16(v - __bfloat162float(h));
}

// ---------------------------------------------------------------------------
// Weight fp32 -> (bf16 hi, bf16 lo). which: 0=wq, 1=wkv, 2=wo
// ---------------------------------------------------------------------------
__global__ void split_w_kernel(const float* __restrict__ src, int which, int off, int n)
{
    int i = blockIdx.x * blockDim.x + threadIdx.x;
    if (i >= n) return;
    __nv_bfloat16 *hi, *lo;
    if (which == 0)      { hi = g_wq_hi;  lo = g_wq_lo;  }
    else if (which == 1) { hi = g_wkv_hi; lo = g_wkv_lo; }
    else                 { hi = g_wo_hi;  lo = g_wo_lo;  }
    split_store(src[i], hi, lo, (long)off + i);
}

// ---------------------------------------------------------------------------
// Depthwise 3x3 conv + folded BN -> bf16 hi/lo split outputs
// ---------------------------------------------------------------------------
__global__ void dwconv_kernel(const float* __restrict__ x, const float* __restrict__ dw,
                              const float* __restrict__ gam, const float* __restrict__ bet,
                              const float* __restrict__ rm, const float* __restrict__ rv,
                              int dst_kv, int off, int stride, int OH)
{
    int idx = blockIdx.x * blockDim.x + threadIdx.x;
    int total = 16 * 256 * OH * OH;
    if (idx >= total) return;
    int ox = idx % OH; int t = idx / OH;
    int oy = t % OH;   t /= OH;
    int c = t & 255;   int b = t >> 8;

    const float* xp = x + ((b << 8) | c) * 1024;
    const float* w  = dw + c * 9;
    int iy0 = oy * stride - 1, ix0 = ox * stride - 1;
    float acc = 0.f;
#pragma unroll
    for (int ky = 0; ky < 3; ky++) {
        int iy = iy0 + ky;
        if ((unsigned)iy < 32u) {
#pragma unroll
            for (int kx = 0; kx < 3; kx++) {
                int ix = ix0 + kx;
                if ((unsigned)ix < 32u) acc += xp[iy * 32 + ix] * w[ky * 3 + kx];
            }
        }
    }
    float inv = gam[c] * rsqrtf(rv[c] + 1e-5f);
    float r = acc * inv + (bet[c] - rm[c] * inv);
    if (dst_kv) split_store(r, g_ykv_hi, g_ykv_lo, (long)off + idx);
    else        split_store(r, g_yq_hi,  g_yq_lo,  (long)off + idx);
}

// ---------------------------------------------------------------------------
// Tensor-core GEMM (3xBF16 split): C[z] = W [M,K] @ B[z] [K,N], z = s*16+b.
// mode 0: W=wq,  B=yq,  out -> g_q scatter    (m = h*64+d)
// mode 1: W=wkv, B=ykv, out -> g_k / g_v
// mode 2: W=wo,  B=o,   out -> Ob row-major + bias
// Block 128x64xK, BK=32, 128 threads (4 warps, 2x2), warp tile 64x32.
// ---------------------------------------------------------------------------
#define BM 128
#define BN 64
#define BK 32

#define MMA_BF16(d, a, b) asm volatile( \
    "mma.sync.aligned.m16n8k16.row.col.f32.bf16.bf16.f32 " \
    "{%0,%1,%2,%3}, {%4,%5,%6,%7}, {%8,%9}, {%0,%1,%2,%3};" \
    : "+f"(d[0]), "+f"(d[1]), "+f"(d[2]), "+f"(d[3]) \
    : "r"(a[0]), "r"(a[1]), "r"(a[2]), "r"(a[3]), "r"(b[0]), "r"(b[1]))

#define LDSM_X4(R, p) { unsigned _ad = (unsigned)__cvta_generic_to_shared(p); \
    asm volatile("ldmatrix.sync.aligned.m8n8.x4.shared.b16 {%0,%1,%2,%3}, [%4];" \
        : "=r"(R[0]), "=r"(R[1]), "=r"(R[2]), "=r"(R[3]) : "r"(_ad)); }

#define LDSM_X2T(R, p) { unsigned _bd = (unsigned)__cvta_generic_to_shared(p); \
    asm volatile("ldmatrix.sync.aligned.m8n8.x2.trans.shared.b16 {%0,%1}, [%2];" \
        : "=r"(R[0]), "=r"(R[1]) : "r"(_bd)); }

__global__ __launch_bounds__(128) void mma_gemm(int M, int N, int K, int mode,
                                                float* __restrict__ Ob,
                                                const float* __restrict__ bias0,
                                                const float* __restrict__ bias1)
{
    __shared__ __align__(16) __nv_bfloat16 sAh[BM][BK + 8], sAl[BM][BK + 8];
    __shared__ __align__(16) __nv_bfloat16 sBh[BK][BN + 8], sBl[BK][BN + 8];

    int z = blockIdx.z, s = z >> 4;
    const __nv_bfloat16 *Ah, *Al, *Bh, *Bl;
    if (mode == 0) {
        Ah = g_wq_hi  + s * 512 * 256;  Al = g_wq_lo  + s * 512 * 256;
        Bh = g_yq_hi  + (long)z * 256 * 1024;  Bl = g_yq_lo  + (long)z * 256 * 1024;
    } else if (mode == 1) {
        Ah = g_wkv_hi + s * 1024 * 256; Al = g_wkv_lo + s * 1024 * 256;
        Bh = g_ykv_hi + (long)z * 256 * 256;   Bl = g_ykv_lo + (long)z * 256 * 256;
    } else {
        Ah = g_wo_hi  + s * 256 * 512;  Al = g_wo_lo  + s * 256 * 512;
        Bh = g_o_hi   + (long)z * 512 * 1024;  Bl = g_o_lo   + (long)z * 512 * 1024;
    }

    int m0 = blockIdx.y * BM, n0 = blockIdx.x * BN;
    int tid = threadIdx.x, lane = tid & 31, wid = tid >> 5;
    int wm = wid >> 1, wn = wid & 1;

    float acc[4][4][4] = {};

    int arow = tid >> 2, acol = (tid & 3) * 8;
    int brow = tid >> 3, bcol = (tid & 7) * 8;
    int lr = lane & 15, lc = (lane >> 4) * 8;

    for (int k0 = 0; k0 < K; k0 += BK) {
#pragma unroll
        for (int r = 0; r < BM; r += 32) {
            *(uint4*)&sAh[arow + r][acol] = *(const uint4*)&Ah[(long)(m0 + arow + r) * K + k0 + acol];
            *(uint4*)&sAl[arow + r][acol] = *(const uint4*)&Al[(long)(m0 + arow + r) * K + k0 + acol];
        }
#pragma unroll
        for (int r = 0; r < BK; r += 16) {
            *(uint4*)&sBh[brow + r][bcol] = *(const uint4*)&Bh[(long)(k0 + brow + r) * N + n0 + bcol];
            *(uint4*)&sBl[brow + r][bcol] = *(const uint4*)&Bl[(long)(k0 + brow + r) * N + n0 + bcol];
        }
        __syncthreads();

#pragma unroll
        for (int kk = 0; kk < BK; kk += 16) {
            uint32_t ah[4][4], al[4][4], bh[4][2], bl[4][2];
#pragma unroll
            for (int mi = 0; mi < 4; mi++) {
                LDSM_X4(ah[mi], &sAh[wm * 64 + mi * 16 + lr][kk + lc]);
                LDSM_X4(al[mi], &sAl[wm * 64 + mi * 16 + lr][kk + lc]);
            }
#pragma unroll
            for (int ni = 0; ni < 4; ni++) {
                LDSM_X2T(bh[ni], &sBh[kk + lr][wn * 32 + ni * 8]);
                LDSM_X2T(bl[ni], &sBl[kk + lr][wn * 32 + ni * 8]);
            }
#pragma unroll
            for (int mi = 0; mi < 4; mi++)
#pragma unroll
                for (int ni = 0; ni < 4; ni++) {
                    MMA_BF16(acc[mi][ni], ah[mi], bh[ni]);
                    MMA_BF16(acc[mi][ni], ah[mi], bl[ni]);
                    MMA_BF16(acc[mi][ni], al[mi], bh[ni]);
                }
        }
        __syncthreads();
    }

    // Epilogue. Fragment: rows r,(r+8); cols cc,cc+1 per (mi,ni).
    int r = lane >> 2, cc = (lane & 3) * 2;
    if (mode == 2) {
        const float* bias = s ? bias1 : bias0;
#pragma unroll
        for (int mi = 0; mi < 4; mi++)
#pragma unroll
            for (int ni = 0; ni < 4; ni++)
#pragma unroll
                for (int half = 0; half < 2; half++) {
                    int m = m0 + wm * 64 + mi * 16 + r + half * 8;
                    int n = n0 + wn * 32 + ni * 8 + cc;
                    float bv = bias[m];
                    float2 v = make_float2(acc[mi][ni][half * 2] + bv,
                                           acc[mi][ni][half * 2 + 1] + bv);
                    *(float2*)&Ob[((long)z * M + m) * N + n] = v;
                }
    } else {
#pragma unroll
        for (int mi = 0; mi < 4; mi++)
#pragma unroll
            for (int ni = 0; ni < 4; ni++)
#pragma unroll
                for (int half = 0; half < 2; half++) {
                    int m = m0 + wm * 64 + mi * 16 + r + half * 8;
                    float* O; int mm = m;
                    if (mode == 0) O = g_q;
                    else if (m < 512) O = g_k;
                    else { O = g_v; mm = m - 512; }
                    long base = ((long)z * 8 + (mm >> 6)) * (long)N * 64 + (mm & 63);
                    int n = n0 + wn * 32 + ni * 8 + cc;
                    O[base + (long)n * 64]       = acc[mi][ni][half * 2];
                    O[base + (long)(n + 1) * 64] = acc[mi][ni][half * 2 + 1];
                }
    }
}

// ---------------------------------------------------------------------------
// Cross attention: o[s] = softmax(q[s] @ k[1-s]^T * 0.125) @ v[1-s]
// One block per (s,b,h). K,V resident in smem (row pad 65). Epilogue writes
// bf16 hi/lo split directly for the out-projection GEMM.
// ---------------------------------------------------------------------------
#define ATT_SMEM_FLOATS (256*65*2 + 8*4*256 + 8*4*64)
#define ATT_SMEM_BYTES  (ATT_SMEM_FLOATS * 4)

__global__ void attn_kernel()
{
    extern __shared__ float sm[];
    float* Ks = sm;
    float* Vs = Ks + 256 * 65;
    float* P  = Vs + 256 * 65;
    float* Qs = P + 8 * 4 * 256;

    int idx = blockIdx.x;            // s*128 + b*8 + h
    int s  = idx >> 7;
    int bh = idx & 127;
    int h  = bh & 7;
    const float* qp = g_q + (long)(s * 128 + bh) * 1024 * 64;
    const float* kp = g_k + (long)((1 - s) * 128 + bh) * 256 * 64;
    const float* vp = g_v + (long)((1 - s) * 128 + bh) * 256 * 64;
    long obase0 = (long)(s * 16 + (bh >> 3)) * 512 * 1024;

    int tid = threadIdx.x, wid = tid >> 5, lane = tid & 31;

    for (int i = tid; i < 4096; i += 256) {
        int j = i >> 4, dq = (i & 15) * 4;
        float4 kt = *(const float4*)&kp[j * 64 + dq];
        float4 vt = *(const float4*)&vp[j * 64 + dq];
        float* kd = &Ks[j * 65 + dq];
        kd[0] = kt.x; kd[1] = kt.y; kd[2] = kt.z; kd[3] = kt.w;
        float* vd = &Vs[j * 65 + dq];
        vd[0] = vt.x; vd[1] = vt.y; vd[2] = vt.z; vd[3] = vt.w;
    }
    __syncthreads();

    float* Pw = P + wid * 4 * 256;
    float* Qw = Qs + wid * 4 * 64;
    const float scale = 0.125f;

    for (int r0 = wid * 4; r0 < 1024; r0 += 32) {
        for (int t2 = lane; t2 < 64; t2 += 32) {
            int r = t2 >> 4, dq = (t2 & 15) * 4;
            float4 qv = *(const float4*)&qp[(long)(r0 + r) * 64 + dq];
            qv.x *= scale; qv.y *= scale; qv.z *= scale; qv.w *= scale;
            *(float4*)&Qw[r * 64 + dq] = qv;
        }
        __syncwarp();

        float dot[4][8];
#pragma unroll
        for (int r = 0; r < 4; r++)
#pragma unroll
            for (int t = 0; t < 8; t++) dot[r][t] = 0.f;

#pragma unroll 4
        for (int d = 0; d < 64; d++) {
            float q0 = Qw[d], q1 = Qw[64 + d], q2 = Qw[128 + d], q3 = Qw[192 + d];
#pragma unroll
            for (int t = 0; t < 8; t++) {
                float kk = Ks[(lane + 32 * t) * 65 + d];
                dot[0][t] += q0 * kk;
                dot[1][t] += q1 * kk;
                dot[2][t] += q2 * kk;
                dot[3][t] += q3 * kk;
            }
        }

#pragma unroll
        for (int r = 0; r < 4; r++) {
            float mx = dot[r][0];
#pragma unroll
            for (int t = 1; t < 8; t++) mx = fmaxf(mx, dot[r][t]);
#pragma unroll
            for (int off = 16; off; off >>= 1)
                mx = fmaxf(mx, __shfl_xor_sync(0xffffffffu, mx, off));
            float sum = 0.f;
#pragma unroll
            for (int t = 0; t < 8; t++) {
                float e = __expf(dot[r][t] - mx);
                dot[r][t] = e;
                sum += e;
            }
#pragma unroll
            for (int off = 16; off; off >>= 1)
                sum += __shfl_xor_sync(0xffffffffu, sum, off);
            float inv = 1.f / sum;
#pragma unroll
            for (int t = 0; t < 8; t++)
                Pw[r * 256 + lane + 32 * t] = dot[r][t] * inv;
        }
        __syncwarp();

        float acc[4][2] = {};
        for (int j = 0; j < 256; j++) {
            float v0 = Vs[j * 65 + lane], v1 = Vs[j * 65 + lane + 32];
            float p0 = Pw[j], p1 = Pw[256 + j], p2 = Pw[512 + j], p3 = Pw[768 + j];
            acc[0][0] += p0 * v0; acc[0][1] += p0 * v1;
            acc[1][0] += p1 * v0; acc[1][1] += p1 * v1;
            acc[2][0] += p2 * v0; acc[2][1] += p2 * v1;
            acc[3][0] += p3 * v0; acc[3][1] += p3 * v1;
        }
        long ob = obase0 + (long)(h * 64 + lane) * 1024;
#pragma unroll
        for (int r = 0; r < 4; r++) {
            split_store(acc[r][0], g_o_hi, g_o_lo, ob + r0 + r);
            split_store(acc[r][1], g_o_hi, g_o_lo, ob + 32 * 1024 + r0 + r);
        }
        __syncwarp();
    }
}

// ---------------------------------------------------------------------------
// Orchestration. Inputs:
// 0 x1, 1 x2, 2..7 q1(dw,g,b,rm,rv,pw), 8..13 kv1, 14..19 q2, 20..25 kv2,
// 26 out1_w, 27 out1_b, 28 out2_w, 29 out2_b
// ---------------------------------------------------------------------------
extern "C" void kernel_launch(void* const* d_in, const int* in_sizes, int n_in,
                              void* d_out, int out_size)
{
    (void)in_sizes; (void)n_in; (void)out_size;
    #define F(i) ((const float*)d_in[i])

    // Split weights to bf16 hi/lo
    split_w_kernel<<<(512*256 + 255) / 256, 256>>>(F(7),  0, 0,         512*256);
    split_w_kernel<<<(512*256 + 255) / 256, 256>>>(F(19), 0, 512*256,   512*256);
    split_w_kernel<<<(1024*256 + 255) / 256, 256>>>(F(13), 1, 0,        1024*256);
    split_w_kernel<<<(1024*256 + 255) / 256, 256>>>(F(25), 1, 1024*256, 1024*256);
    split_w_kernel<<<(256*512 + 255) / 256, 256>>>(F(26), 2, 0,         256*512);
    split_w_kernel<<<(256*512 + 255) / 256, 256>>>(F(28), 2, 256*512,   256*512);

    int tot1 = 16 * 256 * 1024;
    int tot2 = 16 * 256 * 256;
    dwconv_kernel<<<(tot1 + 255) / 256, 256>>>(F(0), F(2),  F(3),  F(4),  F(5),  F(6),  0, 0,    1, 32);
    dwconv_kernel<<<(tot1 + 255) / 256, 256>>>(F(1), F(14), F(15), F(16), F(17), F(18), 0, tot1, 1, 32);
    dwconv_kernel<<<(tot2 + 255) / 256, 256>>>(F(0), F(8),  F(9),  F(10), F(11), F(12), 1, 0,    2, 16);
    dwconv_kernel<<<(tot2 + 255) / 256, 256>>>(F(1), F(20), F(21), F(22), F(23), F(24), 1, tot2, 2, 16);

    // q projection: [512,1024] = Wq[512,256] @ Yq[256,1024]
    mma_gemm<<<dim3(1024 / BN, 512 / BM, 32), 128>>>(512, 1024, 256, 0, nullptr, nullptr, nullptr);
    // kv projection: [1024,256] = Wkv[1024,256] @ Ykv[256,256]
    mma_gemm<<<dim3(256 / BN, 1024 / BM, 32), 128>>>(1024, 256, 256, 1, nullptr, nullptr, nullptr);

    cudaFuncSetAttribute(attn_kernel, cudaFuncAttributeMaxDynamicSharedMemorySize, ATT_SMEM_BYTES);
    attn_kernel<<<256, 256, ATT_SMEM_BYTES>>>();

    // out projection: [256,1024] = Wout[256,512] @ O[512,1024] + bias
    mma_gemm<<<dim3(1024 / BN, 256 / BM, 32), 128>>>(256, 1024, 512, 2, (float*)d_out, F(27), F(29));

    #undef F
}

// round 8
// speedup vs baseline: 2.1805x; 1.8914x over previous
#include <cuda_runtime.h>
#include <cuda_bf16.h>
#include <stdint.h>
#include <math.h>

// ---------------------------------------------------------------------------
// ConvCrossAttention, fully tensorized (mma.sync bf16, 3xBF16 hi/lo split).
// All inter-stage tensors are interleaved bf16 (hi,lo) pairs packed in u32.
// ---------------------------------------------------------------------------

// Scratch (device globals). Element = packed pair: hi | lo<<16.
__device__ unsigned g_yq [2*16*256*1024];  // dwconv q path  [s][b][c][p]
__device__ unsigned g_ykv[2*16*256*256];   // dwconv kv path [s][b][c][j]
__device__ unsigned g_q  [2*16*8*1024*64]; // [s][b][h][p][d]   (scale folded)
__device__ unsigned g_k  [2*16*8*256*64];  // [s][b][h][j][d]
__device__ unsigned g_v  [2*16*8*256*64];
__device__ unsigned g_o  [2*16*512*1024];  // attn out [s][b][c=h*64+d][p]
__device__ __nv_bfloat16 g_wq_hi [2*512*256],  g_wq_lo [2*512*256];
__device__ __nv_bfloat16 g_wkv_hi[2*1024*256], g_wkv_lo[2*1024*256];
__device__ __nv_bfloat16 g_wo_hi [2*256*512],  g_wo_lo [2*256*512];

__device__ __forceinline__ unsigned pack_pair(float v)
{
    __nv_bfloat162 p;
    p.x = __float2bfloat16(v);
    p.y = __float2bfloat16(v - __bfloat162float(p.x));
    return *(unsigned*)&p;
}

// pack (a,b) into a bf16x2 hi word and a bf16x2 lo word (residuals)
__device__ __forceinline__ void pack2(float a, float b, unsigned& hi, unsigned& lo)
{
    __nv_bfloat162 h = __floats2bfloat162_rn(a, b);      // x=a, y=b
    __nv_bfloat162 l = __floats2bfloat162_rn(a - __bfloat162float(h.x),
                                             b - __bfloat162float(h.y));
    hi = *(unsigned*)&h;
    lo = *(unsigned*)&l;
}

// ---------------------------------------------------------------------------
__global__ void split_w_kernel(const float* __restrict__ src, int which, int off,
                               int n, float scale)
{
    int i = blockIdx.x * blockDim.x + threadIdx.x;
    if (i >= n) return;
    __nv_bfloat16 *hi, *lo;
    if (which == 0)      { hi = g_wq_hi;  lo = g_wq_lo;  }
    else if (which == 1) { hi = g_wkv_hi; lo = g_wkv_lo; }
    else                 { hi = g_wo_hi;  lo = g_wo_lo;  }
    float v = src[i] * scale;
    __nv_bfloat16 h = __float2bfloat16(v);
    hi[off + i] = h;
    lo[off + i] = __float2bfloat16(v - __bfloat162float(h));
}

// ---------------------------------------------------------------------------
// Depthwise 3x3 conv + folded BN -> packed pair output
// ---------------------------------------------------------------------------
__global__ void dwconv_kernel(const float* __restrict__ x, const float* __restrict__ dw,
                              const float* __restrict__ gam, const float* __restrict__ bet,
                              const float* __restrict__ rm, const float* __restrict__ rv,
                              int dst_kv, int off, int stride, int OH)
{
    int idx = blockIdx.x * blockDim.x + threadIdx.x;
    int total = 16 * 256 * OH * OH;
    if (idx >= total) return;
    int ox = idx % OH; int t = idx / OH;
    int oy = t % OH;   t /= OH;
    int c = t & 255;   int b = t >> 8;

    const float* xp = x + ((b << 8) | c) * 1024;
    const float* w  = dw + c * 9;
    int iy0 = oy * stride - 1, ix0 = ox * stride - 1;
    float acc = 0.f;
#pragma unroll
    for (int ky = 0; ky < 3; ky++) {
        int iy = iy0 + ky;
        if ((unsigned)iy < 32u) {
#pragma unroll
            for (int kx = 0; kx < 3; kx++) {
                int ix = ix0 + kx;
                if ((unsigned)ix < 32u) acc += xp[iy * 32 + ix] * w[ky * 3 + kx];
            }
        }
    }
    float inv = gam[c] * rsqrtf(rv[c] + 1e-5f);
    float r = acc * inv + (bet[c] - rm[c] * inv);
    unsigned* y = dst_kv ? g_ykv : g_yq;
    y[off + idx] = pack_pair(r);
}

// ---------------------------------------------------------------------------
// MMA primitives
// ---------------------------------------------------------------------------
#define MMA_BF16(d, a, b) asm volatile( \
    "mma.sync.aligned.m16n8k16.row.col.f32.bf16.bf16.f32 " \
    "{%0,%1,%2,%3}, {%4,%5,%6,%7}, {%8,%9}, {%0,%1,%2,%3};" \
    : "+f"(d[0]), "+f"(d[1]), "+f"(d[2]), "+f"(d[3]) \
    : "r"(a[0]), "r"(a[1]), "r"(a[2]), "r"(a[3]), "r"(b[0]), "r"(b[1]))

#define LDSM_X4(R, p) { unsigned _ad = (unsigned)__cvta_generic_to_shared(p); \
    asm volatile("ldmatrix.sync.aligned.m8n8.x4.shared.b16 {%0,%1,%2,%3}, [%4];" \
        : "=r"(R[0]), "=r"(R[1]), "=r"(R[2]), "=r"(R[3]) : "r"(_ad)); }

#define LDSM_X2(R, p) { unsigned _bd = (unsigned)__cvta_generic_to_shared(p); \
    asm volatile("ldmatrix.sync.aligned.m8n8.x2.shared.b16 {%0,%1}, [%2];" \
        : "=r"(R[0]), "=r"(R[1]) : "r"(_bd)); }

#define LDSM_X2T(R, p) { unsigned _bd = (unsigned)__cvta_generic_to_shared(p); \
    asm volatile("ldmatrix.sync.aligned.m8n8.x2.trans.shared.b16 {%0,%1}, [%2];" \
        : "=r"(R[0]), "=r"(R[1]) : "r"(_bd)); }

// ---------------------------------------------------------------------------
// Tensor-core GEMM (3xBF16 split): C[z] = W [M,K] @ B[z] [K,N], z = s*16+b.
// B is interleaved pairs; de-interleaved into sBh/sBl at load.
// mode 0: W=wq,  B=yq (N=1024) -> g_q pairs, coalesced transposed epilogue
// mode 1: W=wkv, B=ykv (N=256) -> g_k / g_v pairs, same epilogue
// mode 2: W=wo,  B=o  (N=1024) -> fp32 row-major + bias (d_out)
// Block 128x64, BK=32, 128 threads (4 warps 2x2), warp tile 64x32.
// ---------------------------------------------------------------------------
#define BM 128
#define BN 64
#define BK 32
#define SA_STR 40
#define SB_STR 72
// dynamic smem: sAh(10240) sAl(10240) sBh(4608) sBl(4608) = 29696; epilogue
// reuses from offset 0 as sC: 128*65*4 = 33280 bytes total.
#define GEMM_SMEM 33280

__global__ __launch_bounds__(128) void mma_gemm(int M, int N, int K, int mode,
                                                float* __restrict__ Ob,
                                                const float* __restrict__ bias0,
                                                const float* __restrict__ bias1)
{
    extern __shared__ char gsm[];
    __nv_bfloat16* sAh = (__nv_bfloat16*)gsm;
    __nv_bfloat16* sAl = (__nv_bfloat16*)(gsm + 10240);
    __nv_bfloat16* sBh = (__nv_bfloat16*)(gsm + 20480);
    __nv_bfloat16* sBl = (__nv_bfloat16*)(gsm + 25088);
    unsigned*      sC  = (unsigned*)gsm;

    int z = blockIdx.z, s = z >> 4;
    const __nv_bfloat16 *Ah, *Al;
    const unsigned* Bp;
    if (mode == 0) {
        Ah = g_wq_hi  + s * 512 * 256;  Al = g_wq_lo  + s * 512 * 256;
        Bp = g_yq  + (long)z * 256 * 1024;
    } else if (mode == 1) {
        Ah = g_wkv_hi + s * 1024 * 256; Al = g_wkv_lo + s * 1024 * 256;
        Bp = g_ykv + (long)z * 256 * 256;
    } else {
        Ah = g_wo_hi  + s * 256 * 512;  Al = g_wo_lo  + s * 256 * 512;
        Bp = g_o   + (long)z * 512 * 1024;
    }

    int m0 = blockIdx.y * BM, n0 = blockIdx.x * BN;
    int tid = threadIdx.x, lane = tid & 31, wid = tid >> 5;
    int wm = wid >> 1, wn = wid & 1;

    float acc[4][4][4] = {};

    int arow = tid >> 2, acol = (tid & 3) * 8;
    int brow = tid >> 3, bcol = (tid & 7) * 8;
    int lr = lane & 15, lc = (lane >> 4) * 8;

    for (int k0 = 0; k0 < K; k0 += BK) {
#pragma unroll
        for (int r = 0; r < BM; r += 32) {
            *(uint4*)&sAh[(arow + r) * SA_STR + acol] = *(const uint4*)&Ah[(long)(m0 + arow + r) * K + k0 + acol];
            *(uint4*)&sAl[(arow + r) * SA_STR + acol] = *(const uint4*)&Al[(long)(m0 + arow + r) * K + k0 + acol];
        }
#pragma unroll
        for (int r = 0; r < BK; r += 16) {
            const unsigned* src = &Bp[(long)(k0 + brow + r) * N + n0 + bcol];
            uint4 u0 = *(const uint4*)src;
            uint4 u1 = *(const uint4*)(src + 4);
            uint4 hv = make_uint4(__byte_perm(u0.x, u0.y, 0x5410), __byte_perm(u0.z, u0.w, 0x5410),
                                  __byte_perm(u1.x, u1.y, 0x5410), __byte_perm(u1.z, u1.w, 0x5410));
            uint4 lv = make_uint4(__byte_perm(u0.x, u0.y, 0x7632), __byte_perm(u0.z, u0.w, 0x7632),
                                  __byte_perm(u1.x, u1.y, 0x7632), __byte_perm(u1.z, u1.w, 0x7632));
            *(uint4*)&sBh[(brow + r) * SB_STR + bcol] = hv;
            *(uint4*)&sBl[(brow + r) * SB_STR + bcol] = lv;
        }
        __syncthreads();

#pragma unroll
        for (int kk = 0; kk < BK; kk += 16) {
            unsigned ah[4][4], al[4][4], bh[4][2], bl[4][2];
#pragma unroll
            for (int mi = 0; mi < 4; mi++) {
                LDSM_X4(ah[mi], &sAh[(wm * 64 + mi * 16 + lr) * SA_STR + kk + lc]);
                LDSM_X4(al[mi], &sAl[(wm * 64 + mi * 16 + lr) * SA_STR + kk + lc]);
            }
#pragma unroll
            for (int ni = 0; ni < 4; ni++) {
                LDSM_X2T(bh[ni], &sBh[(kk + lr) * SB_STR + wn * 32 + ni * 8]);
                LDSM_X2T(bl[ni], &sBl[(kk + lr) * SB_STR + wn * 32 + ni * 8]);
            }
#pragma unroll
            for (int mi = 0; mi < 4; mi++)
#pragma unroll
                for (int ni = 0; ni < 4; ni++) {
                    MMA_BF16(acc[mi][ni], ah[mi], bh[ni]);
                    MMA_BF16(acc[mi][ni], ah[mi], bl[ni]);
                    MMA_BF16(acc[mi][ni], al[mi], bh[ni]);
                }
        }
        __syncthreads();
    }

    int r = lane >> 2, cc = (lane & 3) * 2;
    if (mode == 2) {
        const float* bias = s ? bias1 : bias0;
#pragma unroll
        for (int mi = 0; mi < 4; mi++)
#pragma unroll
            for (int ni = 0; ni < 4; ni++)
#pragma unroll
                for (int half = 0; half < 2; half++) {
                    int m = m0 + wm * 64 + mi * 16 + r + half * 8;
                    int n = n0 + wn * 32 + ni * 8 + cc;
                    float bv = bias[m];
                    float2 v = make_float2(acc[mi][ni][half * 2] + bv,
                                           acc[mi][ni][half * 2 + 1] + bv);
                    *(float2*)&Ob[((long)z * M + m) * N + n] = v;
                }
    } else {
        // stage pairs into sC, then coalesced transposed write
#pragma unroll
        for (int mi = 0; mi < 4; mi++)
#pragma unroll
            for (int ni = 0; ni < 4; ni++)
#pragma unroll
                for (int half = 0; half < 2; half++) {
                    int ml = wm * 64 + mi * 16 + r + half * 8;
                    int nl = wn * 32 + ni * 8 + cc;
                    sC[ml * 65 + nl]     = pack_pair(acc[mi][ni][half * 2]);
                    sC[ml * 65 + nl + 1] = pack_pair(acc[mi][ni][half * 2 + 1]);
                }
        __syncthreads();

        int n = tid & 63, hh = tid >> 6;        // 2 head-rows x 64 columns
        int mrow = m0 + hh * 64;
        unsigned* dst;
        long base;
        if (mode == 0) {
            dst = g_q;
            base = ((long)(z * 8 + (mrow >> 6)) * 1024 + n0 + n) * 64;
        } else if (mrow < 512) {
            dst = g_k;
            base = ((long)(z * 8 + (mrow >> 6)) * 256 + n0 + n) * 64;
        } else {
            dst = g_v;
            base = ((long)(z * 8 + ((mrow - 512) >> 6)) * 256 + n0 + n) * 64;
        }
#pragma unroll
        for (int d4 = 0; d4 < 64; d4 += 4) {
            uint4 t;
            t.x = sC[(hh * 64 + d4 + 0) * 65 + n];
            t.y = sC[(hh * 64 + d4 + 1) * 65 + n];
            t.z = sC[(hh * 64 + d4 + 2) * 65 + n];
            t.w = sC[(hh * 64 + d4 + 3) * 65 + n];
            *(uint4*)&dst[base + d4] = t;
        }
    }
}

// ---------------------------------------------------------------------------
// Tensorized cross attention. One CTA per (s,b,h, q-tile of 128): 2048 CTAs,
// 256 threads (8 warps, each owns 16 q-rows).
// S = Q@K^T (split 3-mma), softmax on fragments, O = P@V (split 3-mma).
// Scale folded into Wq. K/V/Q in smem as separate hi/lo planes, stride 72.
// ---------------------------------------------------------------------------
#define ATT_SMEM 184320   // Kh,Kl,Vh,Vl (4*36864) + max(Qh+Ql 36864, Ost 33280)

__global__ __launch_bounds__(256) void attn_kernel()
{
    extern __shared__ char smx[];
    __nv_bfloat16* Kh = (__nv_bfloat16*)(smx);
    __nv_bfloat16* Kl = (__nv_bfloat16*)(smx + 36864);
    __nv_bfloat16* Vh = (__nv_bfloat16*)(smx + 73728);
    __nv_bfloat16* Vl = (__nv_bfloat16*)(smx + 110592);
    __nv_bfloat16* Qh = (__nv_bfloat16*)(smx + 147456);
    __nv_bfloat16* Ql = (__nv_bfloat16*)(smx + 165888);
    float*        Ost = (float*)(smx + 147456);

    int bid = blockIdx.x;
    int qt = bid & 7, bhs = bid >> 3;
    int s = bhs >> 7, bh = bhs & 127, h = bh & 7, b = bh >> 3;

    const unsigned* qp = g_q + ((long)(s * 128 + bh) * 1024 + qt * 128) * 64;
    const unsigned* kp = g_k + (long)((1 - s) * 128 + bh) * 256 * 64;
    const unsigned* vp = g_v + (long)((1 - s) * 128 + bh) * 256 * 64;

    int tid = threadIdx.x, lane = tid & 31, w = tid >> 5;

    // load K,V (256x64 pairs) and Q (128x64 pairs), de-interleave hi/lo
    for (int c = tid; c < 4096; c += 256) {
        int row = c >> 4, seg = (c & 15) * 4;
        uint4 u = *(const uint4*)&kp[row * 64 + seg];
        *(uint2*)&Kh[row * 72 + seg] = make_uint2(__byte_perm(u.x, u.y, 0x5410), __byte_perm(u.z, u.w, 0x5410));
        *(uint2*)&Kl[row * 72 + seg] = make_uint2(__byte_perm(u.x, u.y, 0x7632), __byte_perm(u.z, u.w, 0x7632));
        u = *(const uint4*)&vp[row * 64 + seg];
        *(uint2*)&Vh[row * 72 + seg] = make_uint2(__byte_perm(u.x, u.y, 0x5410), __byte_perm(u.z, u.w, 0x5410));
        *(uint2*)&Vl[row * 72 + seg] = make_uint2(__byte_perm(u.x, u.y, 0x7632), __byte_perm(u.z, u.w, 0x7632));
    }
    for (int c = tid; c < 2048; c += 256) {
        int row = c >> 4, seg = (c & 15) * 4;
        uint4 u = *(const uint4*)&qp[row * 64 + seg];
        *(uint2*)&Qh[row * 72 + seg] = make_uint2(__byte_perm(u.x, u.y, 0x5410), __byte_perm(u.z, u.w, 0x5410));
        *(uint2*)&Ql[row * 72 + seg] = make_uint2(__byte_perm(u.x, u.y, 0x7632), __byte_perm(u.z, u.w, 0x7632));
    }
    __syncthreads();

    // ---- S = Q @ K^T : warp computes S[16, 256] in sreg[32 ntiles][4]
    float sreg[32][4];
#pragma unroll
    for (int nt = 0; nt < 32; nt++) {
        sreg[nt][0] = 0.f; sreg[nt][1] = 0.f; sreg[nt][2] = 0.f; sreg[nt][3] = 0.f;
    }
    int r0 = w * 16;
    for (int kk = 0; kk < 4; kk++) {
        unsigned ah[4], al[4];
        int qoff = (r0 + (lane & 15)) * 72 + kk * 16 + (lane >> 4) * 8;
        LDSM_X4(ah, &Qh[qoff]);
        LDSM_X4(al, &Ql[qoff]);
        int koff = (lane & 7) * 72 + kk * 16 + ((lane >> 3) & 1) * 8;
#pragma unroll
        for (int nt = 0; nt < 32; nt++) {
            unsigned bh2[2], bl2[2];
            LDSM_X2(bh2, &Kh[nt * 8 * 72 + koff]);
            LDSM_X2(bl2, &Kl[nt * 8 * 72 + koff]);
            MMA_BF16(sreg[nt], ah, bh2);
            MMA_BF16(sreg[nt], ah, bl2);
            MMA_BF16(sreg[nt], al, bh2);
        }
    }

    // ---- softmax on fragments (rows r = lane>>2 and r+8)
    float inv0, inv1;
    {
        float m0 = -1e30f, m1 = -1e30f;
#pragma unroll
        for (int nt = 0; nt < 32; nt++) {
            m0 = fmaxf(m0, fmaxf(sreg[nt][0], sreg[nt][1]));
            m1 = fmaxf(m1, fmaxf(sreg[nt][2], sreg[nt][3]));
        }
        m0 = fmaxf(m0, __shfl_xor_sync(0xffffffffu, m0, 1));
        m0 = fmaxf(m0, __shfl_xor_sync(0xffffffffu, m0, 2));
        m1 = fmaxf(m1, __shfl_xor_sync(0xffffffffu, m1, 1));
        m1 = fmaxf(m1, __shfl_xor_sync(0xffffffffu, m1, 2));
        float s0 = 0.f, s1 = 0.f;
#pragma unroll
        for (int nt = 0; nt < 32; nt++) {
            float e0 = __expf(sreg[nt][0] - m0); sreg[nt][0] = e0; s0 += e0;
            float e1 = __expf(sreg[nt][1] - m0); sreg[nt][1] = e1; s0 += e1;
            float e2 = __expf(sreg[nt][2] - m1); sreg[nt][2] = e2; s1 += e2;
            float e3 = __expf(sreg[nt][3] - m1); sreg[nt][3] = e3; s1 += e3;
        }
        s0 += __shfl_xor_sync(0xffffffffu, s0, 1);
        s0 += __shfl_xor_sync(0xffffffffu, s0, 2);
        s1 += __shfl_xor_sync(0xffffffffu, s1, 1);
        s1 += __shfl_xor_sync(0xffffffffu, s1, 2);
        inv0 = 1.f / s0;
        inv1 = 1.f / s1;
    }

    // ---- O = P @ V : oreg[8 ntiles d][4]
    float oreg[8][4] = {};
#pragma unroll
    for (int kt = 0; kt < 16; kt++) {
        unsigned pah[4], pal[4];
        pack2(sreg[2 * kt][0],     sreg[2 * kt][1],     pah[0], pal[0]);
        pack2(sreg[2 * kt][2],     sreg[2 * kt][3],     pah[1], pal[1]);
        pack2(sreg[2 * kt + 1][0], sreg[2 * kt + 1][1], pah[2], pal[2]);
        pack2(sreg[2 * kt + 1][2], sreg[2 * kt + 1][3], pah[3], pal[3]);
        int voff = (kt * 16 + (lane & 15)) * 72;
#pragma unroll
        for (int nd = 0; nd < 8; nd++) {
            unsigned vh2[2], vl2[2];
            LDSM_X2T(vh2, &Vh[voff + nd * 8]);
            LDSM_X2T(vl2, &Vl[voff + nd * 8]);
            MMA_BF16(oreg[nd], pah, vh2);
            MMA_BF16(oreg[nd], pah, vl2);
            MMA_BF16(oreg[nd], pal, vh2);
        }
    }

    // ---- normalize, stage O[128p][64d] fp32 (reuses Q smem), write transposed
    __syncthreads();
    int r = lane >> 2, cc = (lane & 3) * 2;
#pragma unroll
    for (int nd = 0; nd < 8; nd++) {
        Ost[(r0 + r) * 65 + nd * 8 + cc]         = oreg[nd][0] * inv0;
        Ost[(r0 + r) * 65 + nd * 8 + cc + 1]     = oreg[nd][1] * inv0;
        Ost[(r0 + r + 8) * 65 + nd * 8 + cc]     = oreg[nd][2] * inv1;
        Ost[(r0 + r + 8) * 65 + nd * 8 + cc + 1] = oreg[nd][3] * inv1;
    }
    __syncthreads();

    // coalesced write: warp w handles d rows w, w+8, ..., lane covers 4 p each
    unsigned* op = g_o + ((long)(s * 16 + b) * 512 + h * 64) * 1024 + qt * 128;
    int plane = lane * 4;
    for (int dd = w; dd < 64; dd += 8) {
        uint4 t;
        t.x = pack_pair(Ost[(plane + 0) * 65 + dd]);
        t.y = pack_pair(Ost[(plane + 1) * 65 + dd]);
        t.z = pack_pair(Ost[(plane + 2) * 65 + dd]);
        t.w = pack_pair(Ost[(plane + 3) * 65 + dd]);
        *(uint4*)&op[(long)dd * 1024 + plane] = t;
    }
}

// ---------------------------------------------------------------------------
// Orchestration. Inputs:
// 0 x1, 1 x2, 2..7 q1(dw,g,b,rm,rv,pw), 8..13 kv1, 14..19 q2, 20..25 kv2,
// 26 out1_w, 27 out1_b, 28 out2_w, 29 out2_b
// ---------------------------------------------------------------------------
extern "C" void kernel_launch(void* const* d_in, const int* in_sizes, int n_in,
                              void* d_out, int out_size)
{
    (void)in_sizes; (void)n_in; (void)out_size;
    #define F(i) ((const float*)d_in[i])

    // Weight splits. Softmax scale (1/8) folded into Wq.
    split_w_kernel<<<(512*256 + 255) / 256, 256>>>(F(7),  0, 0,         512*256,  0.125f);
    split_w_kernel<<<(512*256 + 255) / 256, 256>>>(F(19), 0, 512*256,   512*256,  0.125f);
    split_w_kernel<<<(1024*256 + 255) / 256, 256>>>(F(13), 1, 0,        1024*256, 1.0f);
    split_w_kernel<<<(1024*256 + 255) / 256, 256>>>(F(25), 1, 1024*256, 1024*256, 1.0f);
    split_w_kernel<<<(256*512 + 255) / 256, 256>>>(F(26), 2, 0,         256*512,  1.0f);
    split_w_kernel<<<(256*512 + 255) / 256, 256>>>(F(28), 2, 256*512,   256*512,  1.0f);

    int tot1 = 16 * 256 * 1024;
    int tot2 = 16 * 256 * 256;
    dwconv_kernel<<<(tot1 + 255) / 256, 256>>>(F(0), F(2),  F(3),  F(4),  F(5),  F(6),  0, 0,    1, 32);
    dwconv_kernel<<<(tot1 + 255) / 256, 256>>>(F(1), F(14), F(15), F(16), F(17), F(18), 0, tot1, 1, 32);
    dwconv_kernel<<<(tot2 + 255) / 256, 256>>>(F(0), F(8),  F(9),  F(10), F(11), F(12), 1, 0,    2, 16);
    dwconv_kernel<<<(tot2 + 255) / 256, 256>>>(F(1), F(20), F(21), F(22), F(23), F(24), 1, tot2, 2, 16);

    // q projection: [512,1024] = Wq[512,256] @ Yq[256,1024]
    mma_gemm<<<dim3(1024 / BN, 512 / BM, 32), 128, GEMM_SMEM>>>(512, 1024, 256, 0, nullptr, nullptr, nullptr);
    // kv projection: [1024,256] = Wkv[1024,256] @ Ykv[256,256]
    mma_gemm<<<dim3(256 / BN, 1024 / BM, 32), 128, GEMM_SMEM>>>(1024, 256, 256, 1, nullptr, nullptr, nullptr);

    cudaFuncSetAttribute(attn_kernel, cudaFuncAttributeMaxDynamicSharedMemorySize, ATT_SMEM);
    attn_kernel<<<2048, 256, ATT_SMEM>>>();

    // out projection: [256,1024] = Wout[256,512] @ O[512,1024] + bias
    mma_gemm<<<dim3(1024 / BN, 256 / BM, 32), 128, GEMM_SMEM>>>(256, 1024, 512, 2, (float*)d_out, F(27), F(29));

    #undef F
}

// round 9
// speedup vs baseline: 2.2139x; 1.0153x over previous
#include <cuda_runtime.h>
#include <cuda_bf16.h>
#include <stdint.h>
#include <math.h>

// ---------------------------------------------------------------------------
// ConvCrossAttention, fully tensorized (mma.sync bf16, 3xBF16 hi/lo split).
// All inter-stage tensors are interleaved bf16 (hi,lo) pairs packed in u32.
// R9: pipelined GEMM (cp.async + double buffer), x4-paired ldmatrix in attn,
// merged split/dwconv launches (also puts attn at ncu launch index 5).
// ---------------------------------------------------------------------------

__device__ unsigned g_yq [2*16*256*1024];  // dwconv q path  [s][b][c][p]
__device__ unsigned g_ykv[2*16*256*256];   // dwconv kv path [s][b][c][j]
__device__ unsigned g_q  [2*16*8*1024*64]; // [s][b][h][p][d]   (scale folded)
__device__ unsigned g_k  [2*16*8*256*64];  // [s][b][h][j][d]
__device__ unsigned g_v  [2*16*8*256*64];
__device__ unsigned g_o  [2*16*512*1024];  // attn out [s][b][c=h*64+d][p]
__device__ __nv_bfloat16 g_wq_hi [2*512*256],  g_wq_lo [2*512*256];
__device__ __nv_bfloat16 g_wkv_hi[2*1024*256], g_wkv_lo[2*1024*256];
__device__ __nv_bfloat16 g_wo_hi [2*256*512],  g_wo_lo [2*256*512];

__device__ __forceinline__ unsigned pack_pair(float v)
{
    __nv_bfloat162 p;
    p.x = __float2bfloat16(v);
    p.y = __float2bfloat16(v - __bfloat162float(p.x));
    return *(unsigned*)&p;
}

__device__ __forceinline__ void pack2(float a, float b, unsigned& hi, unsigned& lo)
{
    __nv_bfloat162 h = __floats2bfloat162_rn(a, b);
    __nv_bfloat162 l = __floats2bfloat162_rn(a - __bfloat162float(h.x),
                                             b - __bfloat162float(h.y));
    hi = *(unsigned*)&h;
    lo = *(unsigned*)&l;
}

// ---------------------------------------------------------------------------
// All six weight splits in one launch. i in [0, 1048576).
// ---------------------------------------------------------------------------
__global__ void split_all_kernel(const float* __restrict__ wq0, const float* __restrict__ wq1,
                                 const float* __restrict__ wkv0, const float* __restrict__ wkv1,
                                 const float* __restrict__ wo0, const float* __restrict__ wo1)
{
    int i = blockIdx.x * blockDim.x + threadIdx.x;
    const float* src;
    __nv_bfloat16 *hi, *lo;
    int dst;
    float scale = 1.0f;
    if (i < 262144) {                 // wq: 2 x 131072
        int sphase = i >= 131072;
        src = sphase ? wq1 + (i - 131072) : wq0 + i;
        hi = g_wq_hi; lo = g_wq_lo; dst = i; scale = 0.125f;
    } else if (i < 786432) {          // wkv: 2 x 262144
        int j = i - 262144;
        int sphase = j >= 262144;
        src = sphase ? wkv1 + (j - 262144) : wkv0 + j;
        hi = g_wkv_hi; lo = g_wkv_lo; dst = j;
    } else {                          // wo: 2 x 131072
        int j = i - 786432;
        int sphase = j >= 131072;
        src = sphase ? wo1 + (j - 131072) : wo0 + j;
        hi = g_wo_hi; lo = g_wo_lo; dst = j;
    }
    float v = *src * scale;
    __nv_bfloat16 h = __float2bfloat16(v);
    hi[dst] = h;
    lo[dst] = __float2bfloat16(v - __bfloat162float(h));
}

// ---------------------------------------------------------------------------
// Depthwise 3x3 conv + folded BN, both streams in one launch (blockIdx.y).
// ---------------------------------------------------------------------------
__global__ void dwconv2_kernel(const float* __restrict__ x0, const float* __restrict__ x1,
                               const float* __restrict__ dw0, const float* __restrict__ g0,
                               const float* __restrict__ b0, const float* __restrict__ rm0,
                               const float* __restrict__ rv0,
                               const float* __restrict__ dw1, const float* __restrict__ g1,
                               const float* __restrict__ b1, const float* __restrict__ rm1,
                               const float* __restrict__ rv1,
                               int dst_kv, int stride, int OH)
{
    int idx = blockIdx.x * blockDim.x + threadIdx.x;
    int total = 16 * 256 * OH * OH;
    if (idx >= total) return;
    int sp = blockIdx.y;
    const float* x  = sp ? x1 : x0;
    const float* dw = sp ? dw1 : dw0;
    const float* gam = sp ? g1 : g0;
    const float* bet = sp ? b1 : b0;
    const float* rm = sp ? rm1 : rm0;
    const float* rv = sp ? rv1 : rv0;

    int ox = idx % OH; int t = idx / OH;
    int oy = t % OH;   t /= OH;
    int c = t & 255;   int b = t >> 8;

    const float* xp = x + ((b << 8) | c) * 1024;
    const float* w  = dw + c * 9;
    int iy0 = oy * stride - 1, ix0 = ox * stride - 1;
    float acc = 0.f;
#pragma unroll
    for (int ky = 0; ky < 3; ky++) {
        int iy = iy0 + ky;
        if ((unsigned)iy < 32u) {
#pragma unroll
            for (int kx = 0; kx < 3; kx++) {
                int ix = ix0 + kx;
                if ((unsigned)ix < 32u) acc += xp[iy * 32 + ix] * w[ky * 3 + kx];
            }
        }
    }
    float inv = gam[c] * rsqrtf(rv[c] + 1e-5f);
    float r = acc * inv + (bet[c] - rm[c] * inv);
    unsigned* y = dst_kv ? g_ykv : g_yq;
    y[sp * total + idx] = pack_pair(r);
}

// ---------------------------------------------------------------------------
// MMA primitives
// ---------------------------------------------------------------------------
#define MMA_BF16(d, a, b) asm volatile( \
    "mma.sync.aligned.m16n8k16.row.col.f32.bf16.bf16.f32 " \
    "{%0,%1,%2,%3}, {%4,%5,%6,%7}, {%8,%9}, {%0,%1,%2,%3};" \
    : "+f"(d[0]), "+f"(d[1]), "+f"(d[2]), "+f"(d[3]) \
    : "r"(a[0]), "r"(a[1]), "r"(a[2]), "r"(a[3]), "r"(b[0]), "r"(b[1]))

#define LDSM_X4(R, p) { unsigned _ad = (unsigned)__cvta_generic_to_shared(p); \
    asm volatile("ldmatrix.sync.aligned.m8n8.x4.shared.b16 {%0,%1,%2,%3}, [%4];" \
        : "=r"(R[0]), "=r"(R[1]), "=r"(R[2]), "=r"(R[3]) : "r"(_ad)); }

#define LDSM_X4T(R, p) { unsigned _ad = (unsigned)__cvta_generic_to_shared(p); \
    asm volatile("ldmatrix.sync.aligned.m8n8.x4.trans.shared.b16 {%0,%1,%2,%3}, [%4];" \
        : "=r"(R[0]), "=r"(R[1]), "=r"(R[2]), "=r"(R[3]) : "r"(_ad)); }

#define LDSM_X2T(R, p) { unsigned _bd = (unsigned)__cvta_generic_to_shared(p); \
    asm volatile("ldmatrix.sync.aligned.m8n8.x2.trans.shared.b16 {%0,%1}, [%2];" \
        : "=r"(R[0]), "=r"(R[1]) : "r"(_bd)); }

#define CP_ASYNC16(smem_u32, gptr) \
    asm volatile("cp.async.cg.shared.global [%0], [%1], 16;" :: "r"(smem_u32), "l"(gptr))
#define CP_COMMIT() asm volatile("cp.async.commit_group;")
#define CP_WAIT0()  asm volatile("cp.async.wait_group 0;")

// ---------------------------------------------------------------------------
// Pipelined tensor-core GEMM (3xBF16 split): C[z] = W [M,K] @ B[z] [K,N].
// Double-buffered smem; cp.async for A planes, register-staged de-interleave
// for B. One __syncthreads per K-step.
// ---------------------------------------------------------------------------
#define BM 128
#define BN 64
#define BK 32
#define SA_STR 40
#define SB_STR 72
#define BUF_BYTES 29696   // sAh 10240 + sAl 10240 + sBh 4608 + sBl 4608
#define GEMM_SMEM 59392   // 2 buffers; epilogue sC (33280) overlays

__global__ __launch_bounds__(128) void mma_gemm(int M, int N, int K, int mode,
                                                float* __restrict__ Ob,
                                                const float* __restrict__ bias0,
                                                const float* __restrict__ bias1)
{
    extern __shared__ char gsm[];
    unsigned* sC = (unsigned*)gsm;

    int z = blockIdx.z, s = z >> 4;
    const __nv_bfloat16 *Ah, *Al;
    const unsigned* Bp;
    if (mode == 0) {
        Ah = g_wq_hi  + s * 512 * 256;  Al = g_wq_lo  + s * 512 * 256;
        Bp = g_yq  + (long)z * 256 * 1024;
    } else if (mode == 1) {
        Ah = g_wkv_hi + s * 1024 * 256; Al = g_wkv_lo + s * 1024 * 256;
        Bp = g_ykv + (long)z * 256 * 256;
    } else {
        Ah = g_wo_hi  + s * 256 * 512;  Al = g_wo_lo  + s * 256 * 512;
        Bp = g_o   + (long)z * 512 * 1024;
    }

    int m0 = blockIdx.y * BM, n0 = blockIdx.x * BN;
    int tid = threadIdx.x, lane = tid & 31, wid = tid >> 5;
    int wm = wid >> 1, wn = wid & 1;

    float acc[4][4][4] = {};

    int arow = tid >> 2, acol = (tid & 3) * 8;
    int brow = tid >> 3, bcol = (tid & 7) * 8;
    int lr = lane & 15, lc = (lane >> 4) * 8;

    __nv_bfloat16* pAh[2] = {(__nv_bfloat16*)gsm, (__nv_bfloat16*)(gsm + BUF_BYTES)};
    __nv_bfloat16* pAl[2] = {(__nv_bfloat16*)(gsm + 10240), (__nv_bfloat16*)(gsm + BUF_BYTES + 10240)};
    __nv_bfloat16* pBh[2] = {(__nv_bfloat16*)(gsm + 20480), (__nv_bfloat16*)(gsm + BUF_BYTES + 20480)};
    __nv_bfloat16* pBl[2] = {(__nv_bfloat16*)(gsm + 25088), (__nv_bfloat16*)(gsm + BUF_BYTES + 25088)};

    uint4 stB[4];
    int nk = K / BK;

    // ---- prologue: fill buffer 0
    {
#pragma unroll
        for (int r = 0; r < 4; r++) {
            unsigned d0 = (unsigned)__cvta_generic_to_shared(&pAh[0][(arow + 32 * r) * SA_STR + acol]);
            unsigned d1 = (unsigned)__cvta_generic_to_shared(&pAl[0][(arow + 32 * r) * SA_STR + acol]);
            CP_ASYNC16(d0, &Ah[(long)(m0 + arow + 32 * r) * K + acol]);
            CP_ASYNC16(d1, &Al[(long)(m0 + arow + 32 * r) * K + acol]);
        }
        CP_COMMIT();
#pragma unroll
        for (int r = 0; r < 2; r++) {
            const unsigned* src = &Bp[(long)(brow + 16 * r) * N + n0 + bcol];
            stB[2 * r]     = *(const uint4*)src;
            stB[2 * r + 1] = *(const uint4*)(src + 4);
        }
#pragma unroll
        for (int r = 0; r < 2; r++) {
            uint4 u0 = stB[2 * r], u1 = stB[2 * r + 1];
            uint4 hv = make_uint4(__byte_perm(u0.x, u0.y, 0x5410), __byte_perm(u0.z, u0.w, 0x5410),
                                  __byte_perm(u1.x, u1.y, 0x5410), __byte_perm(u1.z, u1.w, 0x5410));
            uint4 lv = make_uint4(__byte_perm(u0.x, u0.y, 0x7632), __byte_perm(u0.z, u0.w, 0x7632),
                                  __byte_perm(u1.x, u1.y, 0x7632), __byte_perm(u1.z, u1.w, 0x7632));
            *(uint4*)&pBh[0][(brow + 16 * r) * SB_STR + bcol] = hv;
            *(uint4*)&pBl[0][(brow + 16 * r) * SB_STR + bcol] = lv;
        }
        CP_WAIT0();
        __syncthreads();
    }

    for (int i = 0; i < nk; i++) {
        int cur = i & 1, nxt = cur ^ 1;
        bool has_next = (i + 1 < nk);
        if (has_next) {
            int k0 = (i + 1) * BK;
#pragma unroll
            for (int r = 0; r < 4; r++) {
                unsigned d0 = (unsigned)__cvta_generic_to_shared(&pAh[nxt][(arow + 32 * r) * SA_STR + acol]);
                unsigned d1 = (unsigned)__cvta_generic_to_shared(&pAl[nxt][(arow + 32 * r) * SA_STR + acol]);
                CP_ASYNC16(d0, &Ah[(long)(m0 + arow + 32 * r) * K + k0 + acol]);
                CP_ASYNC16(d1, &Al[(long)(m0 + arow + 32 * r) * K + k0 + acol]);
            }
            CP_COMMIT();
#pragma unroll
            for (int r = 0; r < 2; r++) {
                const unsigned* src = &Bp[(long)(k0 + brow + 16 * r) * N + n0 + bcol];
                stB[2 * r]     = *(const uint4*)src;
                stB[2 * r + 1] = *(const uint4*)(src + 4);
            }
        }

        // compute on buffer cur
#pragma unroll
        for (int kk = 0; kk < BK; kk += 16) {
            unsigned ah[4][4], al[4][4], bh[4][2], bl[4][2];
#pragma unroll
            for (int mi = 0; mi < 4; mi++) {
                LDSM_X4(ah[mi], &pAh[cur][(wm * 64 + mi * 16 + lr) * SA_STR + kk + lc]);
                LDSM_X4(al[mi], &pAl[cur][(wm * 64 + mi * 16 + lr) * SA_STR + kk + lc]);
            }
#pragma unroll
            for (int ni = 0; ni < 4; ni++) {
                LDSM_X2T(bh[ni], &pBh[cur][(kk + lr) * SB_STR + wn * 32 + ni * 8]);
                LDSM_X2T(bl[ni], &pBl[cur][(kk + lr) * SB_STR + wn * 32 + ni * 8]);
            }
#pragma unroll
            for (int mi = 0; mi < 4; mi++)
#pragma unroll
                for (int ni = 0; ni < 4; ni++) {
                    MMA_BF16(acc[mi][ni], ah[mi], bh[ni]);
                    MMA_BF16(acc[mi][ni], ah[mi], bl[ni]);
                    MMA_BF16(acc[mi][ni], al[mi], bh[ni]);
                }
        }

        if (has_next) {
#pragma unroll
            for (int r = 0; r < 2; r++) {
                uint4 u0 = stB[2 * r], u1 = stB[2 * r + 1];
                uint4 hv = make_uint4(__byte_perm(u0.x, u0.y, 0x5410), __byte_perm(u0.z, u0.w, 0x5410),
                                      __byte_perm(u1.x, u1.y, 0x5410), __byte_perm(u1.z, u1.w, 0x5410));
                uint4 lv = make_uint4(__byte_perm(u0.x, u0.y, 0x7632), __byte_perm(u0.z, u0.w, 0x7632),
                                      __byte_perm(u1.x, u1.y, 0x7632), __byte_perm(u1.z, u1.w, 0x7632));
                *(uint4*)&pBh[nxt][(brow + 16 * r) * SB_STR + bcol] = hv;
                *(uint4*)&pBl[nxt][(brow + 16 * r) * SB_STR + bcol] = lv;
            }
            CP_WAIT0();
        }
        __syncthreads();
    }

    int r = lane >> 2, cc = (lane & 3) * 2;
    if (mode == 2) {
        const float* bias = s ? bias1 : bias0;
#pragma unroll
        for (int mi = 0; mi < 4; mi++)
#pragma unroll
            for (int ni = 0; ni < 4; ni++)
#pragma unroll
                for (int half = 0; half < 2; half++) {
                    int m = m0 + wm * 64 + mi * 16 + r + half * 8;
                    int n = n0 + wn * 32 + ni * 8 + cc;
                    float bv = bias[m];
                    float2 v = make_float2(acc[mi][ni][half * 2] + bv,
                                           acc[mi][ni][half * 2 + 1] + bv);
                    *(float2*)&Ob[((long)z * M + m) * N + n] = v;
                }
    } else {
#pragma unroll
        for (int mi = 0; mi < 4; mi++)
#pragma unroll
            for (int ni = 0; ni < 4; ni++)
#pragma unroll
                for (int half = 0; half < 2; half++) {
                    int ml = wm * 64 + mi * 16 + r + half * 8;
                    int nl = wn * 32 + ni * 8 + cc;
                    sC[ml * 65 + nl]     = pack_pair(acc[mi][ni][half * 2]);
                    sC[ml * 65 + nl + 1] = pack_pair(acc[mi][ni][half * 2 + 1]);
                }
        __syncthreads();

        int n = tid & 63, hh = tid >> 6;
        int mrow = m0 + hh * 64;
        unsigned* dst;
        long base;
        if (mode == 0) {
            dst = g_q;
            base = ((long)(z * 8 + (mrow >> 6)) * 1024 + n0 + n) * 64;
        } else if (mrow < 512) {
            dst = g_k;
            base = ((long)(z * 8 + (mrow >> 6)) * 256 + n0 + n) * 64;
        } else {
            dst = g_v;
            base = ((long)(z * 8 + ((mrow - 512) >> 6)) * 256 + n0 + n) * 64;
        }
#pragma unroll
        for (int d4 = 0; d4 < 64; d4 += 4) {
            uint4 t;
            t.x = sC[(hh * 64 + d4 + 0) * 65 + n];
            t.y = sC[(hh * 64 + d4 + 1) * 65 + n];
            t.z = sC[(hh * 64 + d4 + 2) * 65 + n];
            t.w = sC[(hh * 64 + d4 + 3) * 65 + n];
            *(uint4*)&dst[base + d4] = t;
        }
    }
}

// ---------------------------------------------------------------------------
// Tensorized cross attention (x4-paired ldmatrix).
// ---------------------------------------------------------------------------
#define ATT_SMEM 184320

__global__ __launch_bounds__(256) void attn_kernel()
{
    extern __shared__ char smx[];
    __nv_bfloat16* Kh = (__nv_bfloat16*)(smx);
    __nv_bfloat16* Kl = (__nv_bfloat16*)(smx + 36864);
    __nv_bfloat16* Vh = (__nv_bfloat16*)(smx + 73728);
    __nv_bfloat16* Vl = (__nv_bfloat16*)(smx + 110592);
    __nv_bfloat16* Qh = (__nv_bfloat16*)(smx + 147456);
    __nv_bfloat16* Ql = (__nv_bfloat16*)(smx + 165888);
    float*        Ost = (float*)(smx + 147456);

    int bid = blockIdx.x;
    int qt = bid & 7, bhs = bid >> 3;
    int s = bhs >> 7, bh = bhs & 127, h = bh & 7, b = bh >> 3;

    const unsigned* qp = g_q + ((long)(s * 128 + bh) * 1024 + qt * 128) * 64;
    const unsigned* kp = g_k + (long)((1 - s) * 128 + bh) * 256 * 64;
    const unsigned* vp = g_v + (long)((1 - s) * 128 + bh) * 256 * 64;

    int tid = threadIdx.x, lane = tid & 31, w = tid >> 5;

    for (int c = tid; c < 4096; c += 256) {
        int row = c >> 4, seg = (c & 15) * 4;
        uint4 u = *(const uint4*)&kp[row * 64 + seg];
        *(uint2*)&Kh[row * 72 + seg] = make_uint2(__byte_perm(u.x, u.y, 0x5410), __byte_perm(u.z, u.w, 0x5410));
        *(uint2*)&Kl[row * 72 + seg] = make_uint2(__byte_perm(u.x, u.y, 0x7632), __byte_perm(u.z, u.w, 0x7632));
        u = *(const uint4*)&vp[row * 64 + seg];
        *(uint2*)&Vh[row * 72 + seg] = make_uint2(__byte_perm(u.x, u.y, 0x5410), __byte_perm(u.z, u.w, 0x5410));
        *(uint2*)&Vl[row * 72 + seg] = make_uint2(__byte_perm(u.x, u.y, 0x7632), __byte_perm(u.z, u.w, 0x7632));
    }
    for (int c = tid; c < 2048; c += 256) {
        int row = c >> 4, seg = (c & 15) * 4;
        uint4 u = *(const uint4*)&qp[row * 64 + seg];
        *(uint2*)&Qh[row * 72 + seg] = make_uint2(__byte_perm(u.x, u.y, 0x5410), __byte_perm(u.z, u.w, 0x5410));
        *(uint2*)&Ql[row * 72 + seg] = make_uint2(__byte_perm(u.x, u.y, 0x7632), __byte_perm(u.z, u.w, 0x7632));
    }
    __syncthreads();

    // ---- S = Q @ K^T
    float sreg[32][4];
#pragma unroll
    for (int nt = 0; nt < 32; nt++) {
        sreg[nt][0] = 0.f; sreg[nt][1] = 0.f; sreg[nt][2] = 0.f; sreg[nt][3] = 0.f;
    }
    int r0 = w * 16;
    int krow = (lane & 7) + ((lane >> 4) << 3);
    for (int kk = 0; kk < 4; kk++) {
        unsigned ah[4], al[4];
        int qoff = (r0 + (lane & 15)) * 72 + kk * 16 + (lane >> 4) * 8;
        LDSM_X4(ah, &Qh[qoff]);
        LDSM_X4(al, &Ql[qoff]);
        int koff = kk * 16 + ((lane >> 3) & 1) * 8;
#pragma unroll
        for (int nt2 = 0; nt2 < 16; nt2++) {
            unsigned kh4[4], kl4[4];
            LDSM_X4(kh4, &Kh[(nt2 * 16 + krow) * 72 + koff]);
            LDSM_X4(kl4, &Kl[(nt2 * 16 + krow) * 72 + koff]);
            MMA_BF16(sreg[2 * nt2],     ah, (kh4 + 0));
            MMA_BF16(sreg[2 * nt2],     ah, (kl4 + 0));
            MMA_BF16(sreg[2 * nt2],     al, (kh4 + 0));
            MMA_BF16(sreg[2 * nt2 + 1], ah, (kh4 + 2));
            MMA_BF16(sreg[2 * nt2 + 1], ah, (kl4 + 2));
            MMA_BF16(sreg[2 * nt2 + 1], al, (kh4 + 2));
        }
    }

    // ---- softmax on fragments
    float inv0, inv1;
    {
        float m0 = -1e30f, m1 = -1e30f;
#pragma unroll
        for (int nt = 0; nt < 32; nt++) {
            m0 = fmaxf(m0, fmaxf(sreg[nt][0], sreg[nt][1]));
            m1 = fmaxf(m1, fmaxf(sreg[nt][2], sreg[nt][3]));
        }
        m0 = fmaxf(m0, __shfl_xor_sync(0xffffffffu, m0, 1));
        m0 = fmaxf(m0, __shfl_xor_sync(0xffffffffu, m0, 2));
        m1 = fmaxf(m1, __shfl_xor_sync(0xffffffffu, m1, 1));
        m1 = fmaxf(m1, __shfl_xor_sync(0xffffffffu, m1, 2));
        float s0 = 0.f, s1 = 0.f;
#pragma unroll
        for (int nt = 0; nt < 32; nt++) {
            float e0 = __expf(sreg[nt][0] - m0); sreg[nt][0] = e0; s0 += e0;
            float e1 = __expf(sreg[nt][1] - m0); sreg[nt][1] = e1; s0 += e1;
            float e2 = __expf(sreg[nt][2] - m1); sreg[nt][2] = e2; s1 += e2;
            float e3 = __expf(sreg[nt][3] - m1); sreg[nt][3] = e3; s1 += e3;
        }
        s0 += __shfl_xor_sync(0xffffffffu, s0, 1);
        s0 += __shfl_xor_sync(0xffffffffu, s0, 2);
        s1 += __shfl_xor_sync(0xffffffffu, s1, 1);
        s1 += __shfl_xor_sync(0xffffffffu, s1, 2);
        inv0 = 1.f / s0;
        inv1 = 1.f / s1;
    }

    // ---- O = P @ V
    float oreg[8][4] = {};
#pragma unroll
    for (int kt = 0; kt < 16; kt++) {
        unsigned pah[4], pal[4];
        pack2(sreg[2 * kt][0],     sreg[2 * kt][1],     pah[0], pal[0]);
        pack2(sreg[2 * kt][2],     sreg[2 * kt][3],     pah[1], pal[1]);
        pack2(sreg[2 * kt + 1][0], sreg[2 * kt + 1][1], pah[2], pal[2]);
        pack2(sreg[2 * kt + 1][2], sreg[2 * kt + 1][3], pah[3], pal[3]);
        int vrow = kt * 16 + (lane & 7) + ((lane >> 3) & 1) * 8;
        int vcol = (lane >> 4) << 3;
#pragma unroll
        for (int nd2 = 0; nd2 < 4; nd2++) {
            unsigned vh4[4], vl4[4];
            LDSM_X4T(vh4, &Vh[vrow * 72 + nd2 * 16 + vcol]);
            LDSM_X4T(vl4, &Vl[vrow * 72 + nd2 * 16 + vcol]);
            MMA_BF16(oreg[2 * nd2],     pah, (vh4 + 0));
            MMA_BF16(oreg[2 * nd2],     pah, (vl4 + 0));
            MMA_BF16(oreg[2 * nd2],     pal, (vh4 + 0));
            MMA_BF16(oreg[2 * nd2 + 1], pah, (vh4 + 2));
            MMA_BF16(oreg[2 * nd2 + 1], pah, (vl4 + 2));
            MMA_BF16(oreg[2 * nd2 + 1], pal, (vh4 + 2));
        }
    }

    // ---- normalize, stage, transposed coalesced write
    __syncthreads();
    int r = lane >> 2, cc = (lane & 3) * 2;
#pragma unroll
    for (int nd = 0; nd < 8; nd++) {
        Ost[(r0 + r) * 65 + nd * 8 + cc]         = oreg[nd][0] * inv0;
        Ost[(r0 + r) * 65 + nd * 8 + cc + 1]     = oreg[nd][1] * inv0;
        Ost[(r0 + r + 8) * 65 + nd * 8 + cc]     = oreg[nd][2] * inv1;
        Ost[(r0 + r + 8) * 65 + nd * 8 + cc + 1] = oreg[nd][3] * inv1;
    }
    __syncthreads();

    unsigned* op = g_o + ((long)(s * 16 + b) * 512 + h * 64) * 1024 + qt * 128;
    int plane = lane * 4;
    for (int dd = w; dd < 64; dd += 8) {
        uint4 t;
        t.x = pack_pair(Ost[(plane + 0) * 65 + dd]);
        t.y = pack_pair(Ost[(plane + 1) * 65 + dd]);
        t.z = pack_pair(Ost[(plane + 2) * 65 + dd]);
        t.w = pack_pair(Ost[(plane + 3) * 65 + dd]);
        *(uint4*)&op[(long)dd * 1024 + plane] = t;
    }
}

// ---------------------------------------------------------------------------
// Orchestration. Launch order puts attn at index 5 for the fixed ncu window.
// Inputs: 0 x1, 1 x2, 2..7 q1(dw,g,b,rm,rv,pw), 8..13 kv1, 14..19 q2,
// 20..25 kv2, 26 out1_w, 27 out1_b, 28 out2_w, 29 out2_b
// ---------------------------------------------------------------------------
extern "C" void kernel_launch(void* const* d_in, const int* in_sizes, int n_in,
                              void* d_out, int out_size)
{
    (void)in_sizes; (void)n_in; (void)out_size;
    #define F(i) ((const float*)d_in[i])

    cudaFuncSetAttribute(mma_gemm, cudaFuncAttributeMaxDynamicSharedMemorySize, GEMM_SMEM);
    cudaFuncSetAttribute(attn_kernel, cudaFuncAttributeMaxDynamicSharedMemorySize, ATT_SMEM);

    // 0: weight splits (scale 1/8 folded into Wq)
    split_all_kernel<<<4096, 256>>>(F(7), F(19), F(13), F(25), F(26), F(28));

    // 1-2: depthwise convs, both streams per launch
    int tot1 = 16 * 256 * 1024;
    int tot2 = 16 * 256 * 256;
    dwconv2_kernel<<<dim3((tot1 + 255) / 256, 2), 256>>>(
        F(0), F(1), F(2), F(3), F(4), F(5), F(6),
        F(14), F(15), F(16), F(17), F(18), 0, 1, 32);
    dwconv2_kernel<<<dim3((tot2 + 255) / 256, 2), 256>>>(
        F(0), F(1), F(8), F(9), F(10), F(11), F(12),
        F(20), F(21), F(22), F(23), F(24), 1, 2, 16);

    // 3: q projection  [512,1024] = Wq @ Yq
    mma_gemm<<<dim3(1024 / BN, 512 / BM, 32), 128, GEMM_SMEM>>>(512, 1024, 256, 0, nullptr, nullptr, nullptr);
    // 4: kv projection [1024,256] = Wkv @ Ykv
    mma_gemm<<<dim3(256 / BN, 1024 / BM, 32), 128, GEMM_SMEM>>>(1024, 256, 256, 1, nullptr, nullptr, nullptr);

    // 5: attention (profiled by ncu -s 5 -c 1)
    attn_kernel<<<2048, 256, ATT_SMEM>>>();

    // 6: out projection [256,1024] = Wout @ O + bias
    mma_gemm<<<dim3(1024 / BN, 256 / BM, 32), 128, GEMM_SMEM>>>(256, 1024, 512, 2, (float*)d_out, F(27), F(29));

    #undef F
}

// round 10
// speedup vs baseline: 2.3104x; 1.0436x over previous
#include <cuda_runtime.h>
#include <cuda_bf16.h>
#include <stdint.h>
#include <math.h>

// ---------------------------------------------------------------------------
// ConvCrossAttention, fully tensorized (mma.sync bf16, 3xBF16 hi/lo split).
// R10: GEMM widened to 128x128 tiles, 256 threads, x4T-paired B fragments.
// ---------------------------------------------------------------------------

__device__ unsigned g_yq [2*16*256*1024];  // dwconv q path  [s][b][c][p]
__device__ unsigned g_ykv[2*16*256*256];   // dwconv kv path [s][b][c][j]
__device__ unsigned g_q  [2*16*8*1024*64]; // [s][b][h][p][d]   (scale folded)
__device__ unsigned g_k  [2*16*8*256*64];
__device__ unsigned g_v  [2*16*8*256*64];
__device__ unsigned g_o  [2*16*512*1024];  // attn out [s][b][c=h*64+d][p]
__device__ __nv_bfloat16 g_wq_hi [2*512*256],  g_wq_lo [2*512*256];
__device__ __nv_bfloat16 g_wkv_hi[2*1024*256], g_wkv_lo[2*1024*256];
__device__ __nv_bfloat16 g_wo_hi [2*256*512],  g_wo_lo [2*256*512];

__device__ __forceinline__ unsigned pack_pair(float v)
{
    __nv_bfloat162 p;
    p.x = __float2bfloat16(v);
    p.y = __float2bfloat16(v - __bfloat162float(p.x));
    return *(unsigned*)&p;
}

__device__ __forceinline__ void pack2(float a, float b, unsigned& hi, unsigned& lo)
{
    __nv_bfloat162 h = __floats2bfloat162_rn(a, b);
    __nv_bfloat162 l = __floats2bfloat162_rn(a - __bfloat162float(h.x),
                                             b - __bfloat162float(h.y));
    hi = *(unsigned*)&h;
    lo = *(unsigned*)&l;
}

// ---------------------------------------------------------------------------
__global__ void split_all_kernel(const float* __restrict__ wq0, const float* __restrict__ wq1,
                                 const float* __restrict__ wkv0, const float* __restrict__ wkv1,
                                 const float* __restrict__ wo0, const float* __restrict__ wo1)
{
    int i = blockIdx.x * blockDim.x + threadIdx.x;
    const float* src;
    __nv_bfloat16 *hi, *lo;
    int dst;
    float scale = 1.0f;
    if (i < 262144) {
        int sphase = i >= 131072;
        src = sphase ? wq1 + (i - 131072) : wq0 + i;
        hi = g_wq_hi; lo = g_wq_lo; dst = i; scale = 0.125f;
    } else if (i < 786432) {
        int j = i - 262144;
        int sphase = j >= 262144;
        src = sphase ? wkv1 + (j - 262144) : wkv0 + j;
        hi = g_wkv_hi; lo = g_wkv_lo; dst = j;
    } else {
        int j = i - 786432;
        int sphase = j >= 131072;
        src = sphase ? wo1 + (j - 131072) : wo0 + j;
        hi = g_wo_hi; lo = g_wo_lo; dst = j;
    }
    float v = *src * scale;
    __nv_bfloat16 h = __float2bfloat16(v);
    hi[dst] = h;
    lo[dst] = __float2bfloat16(v - __bfloat162float(h));
}

// ---------------------------------------------------------------------------
__global__ void dwconv2_kernel(const float* __restrict__ x0, const float* __restrict__ x1,
                               const float* __restrict__ dw0, const float* __restrict__ g0,
                               const float* __restrict__ b0, const float* __restrict__ rm0,
                               const float* __restrict__ rv0,
                               const float* __restrict__ dw1, const float* __restrict__ g1,
                               const float* __restrict__ b1, const float* __restrict__ rm1,
                               const float* __restrict__ rv1,
                               int dst_kv, int stride, int OH)
{
    int idx = blockIdx.x * blockDim.x + threadIdx.x;
    int total = 16 * 256 * OH * OH;
    if (idx >= total) return;
    int sp = blockIdx.y;
    const float* x  = sp ? x1 : x0;
    const float* dw = sp ? dw1 : dw0;
    const float* gam = sp ? g1 : g0;
    const float* bet = sp ? b1 : b0;
    const float* rm = sp ? rm1 : rm0;
    const float* rv = sp ? rv1 : rv0;

    int ox = idx % OH; int t = idx / OH;
    int oy = t % OH;   t /= OH;
    int c = t & 255;   int b = t >> 8;

    const float* xp = x + ((b << 8) | c) * 1024;
    const float* w  = dw + c * 9;
    int iy0 = oy * stride - 1, ix0 = ox * stride - 1;
    float acc = 0.f;
#pragma unroll
    for (int ky = 0; ky < 3; ky++) {
        int iy = iy0 + ky;
        if ((unsigned)iy < 32u) {
#pragma unroll
            for (int kx = 0; kx < 3; kx++) {
                int ix = ix0 + kx;
                if ((unsigned)ix < 32u) acc += xp[iy * 32 + ix] * w[ky * 3 + kx];
            }
        }
    }
    float inv = gam[c] * rsqrtf(rv[c] + 1e-5f);
    float r = acc * inv + (bet[c] - rm[c] * inv);
    unsigned* y = dst_kv ? g_ykv : g_yq;
    y[sp * total + idx] = pack_pair(r);
}

// ---------------------------------------------------------------------------
// MMA primitives
// ---------------------------------------------------------------------------
#define MMA_BF16(d, a, b) asm volatile( \
    "mma.sync.aligned.m16n8k16.row.col.f32.bf16.bf16.f32 " \
    "{%0,%1,%2,%3}, {%4,%5,%6,%7}, {%8,%9}, {%0,%1,%2,%3};" \
    : "+f"(d[0]), "+f"(d[1]), "+f"(d[2]), "+f"(d[3]) \
    : "r"(a[0]), "r"(a[1]), "r"(a[2]), "r"(a[3]), "r"(b[0]), "r"(b[1]))

#define LDSM_X4(R, p) { unsigned _ad = (unsigned)__cvta_generic_to_shared(p); \
    asm volatile("ldmatrix.sync.aligned.m8n8.x4.shared.b16 {%0,%1,%2,%3}, [%4];" \
        : "=r"(R[0]), "=r"(R[1]), "=r"(R[2]), "=r"(R[3]) : "r"(_ad)); }

#define LDSM_X4T(R, p) { unsigned _ad = (unsigned)__cvta_generic_to_shared(p); \
    asm volatile("ldmatrix.sync.aligned.m8n8.x4.trans.shared.b16 {%0,%1,%2,%3}, [%4];" \
        : "=r"(R[0]), "=r"(R[1]), "=r"(R[2]), "=r"(R[3]) : "r"(_ad)); }

#define CP_ASYNC16(smem_u32, gptr) \
    asm volatile("cp.async.cg.shared.global [%0], [%1], 16;" :: "r"(smem_u32), "l"(gptr))
#define CP_COMMIT() asm volatile("cp.async.commit_group;")
#define CP_WAIT0()  asm volatile("cp.async.wait_group 0;")

// ---------------------------------------------------------------------------
// Pipelined tensor-core GEMM (3xBF16 split): C[z] = W [M,K] @ B[z] [K,N].
// 128x128 tile, BK=32, 256 threads (8 warps 2x4), warp tile 64x32.
// ---------------------------------------------------------------------------
#define BM 128
#define BN 128
#define BK 32
#define SA_STR 40
#define SB_STR 136
#define A_PLANE 10240     // 128*40*2
#define B_PLANE 8704      // 32*136*2
#define BUF_BYTES 37888   // 2*A_PLANE + 2*B_PLANE
#define GEMM_SMEM 75776   // 2 buffers; epilogue sC (128*129*4=66048) overlays

__global__ __launch_bounds__(256) void mma_gemm(int M, int N, int K, int mode,
                                                float* __restrict__ Ob,
                                                const float* __restrict__ bias0,
                                                const float* __restrict__ bias1)
{
    extern __shared__ char gsm[];
    unsigned* sC = (unsigned*)gsm;

    int z = blockIdx.z, s = z >> 4;
    const __nv_bfloat16 *Ah, *Al;
    const unsigned* Bp;
    if (mode == 0) {
        Ah = g_wq_hi  + s * 512 * 256;  Al = g_wq_lo  + s * 512 * 256;
        Bp = g_yq  + (long)z * 256 * 1024;
    } else if (mode == 1) {
        Ah = g_wkv_hi + s * 1024 * 256; Al = g_wkv_lo + s * 1024 * 256;
        Bp = g_ykv + (long)z * 256 * 256;
    } else {
        Ah = g_wo_hi  + s * 256 * 512;  Al = g_wo_lo  + s * 256 * 512;
        Bp = g_o   + (long)z * 512 * 1024;
    }

    int m0 = blockIdx.y * BM, n0 = blockIdx.x * BN;
    int tid = threadIdx.x, lane = tid & 31, wid = tid >> 5;
    int wm = wid >> 2, wn = wid & 3;

    float acc[4][4][4] = {};

    // A cp.async: thread -> 2 rows (64B apart), 16B segment
    int arow = tid >> 2, acol = (tid & 3) * 8;
    // A ldsm
    int lr = lane & 15, lc = (lane >> 4) * 8;
    // B ldsm (x4T pairing)
    int brow2 = (lane & 7) + ((lane >> 3) & 1) * 8;
    int bcol2 = (lane >> 4) * 8;

    __nv_bfloat16* pAh[2] = {(__nv_bfloat16*)gsm, (__nv_bfloat16*)(gsm + BUF_BYTES)};
    __nv_bfloat16* pAl[2] = {(__nv_bfloat16*)(gsm + A_PLANE), (__nv_bfloat16*)(gsm + BUF_BYTES + A_PLANE)};
    __nv_bfloat16* pBh[2] = {(__nv_bfloat16*)(gsm + 2*A_PLANE), (__nv_bfloat16*)(gsm + BUF_BYTES + 2*A_PLANE)};
    __nv_bfloat16* pBl[2] = {(__nv_bfloat16*)(gsm + 2*A_PLANE + B_PLANE), (__nv_bfloat16*)(gsm + BUF_BYTES + 2*A_PLANE + B_PLANE)};

    uint4 stB[4];
    int nk = K / BK;

    // B seg assignment: s_j = tid + 256*j, row = s>>4, col = (s&15)*8 (u32)
    int bR[2], bC[2];
#pragma unroll
    for (int j = 0; j < 2; j++) { int sj = tid + 256 * j; bR[j] = sj >> 4; bC[j] = (sj & 15) * 8; }

    // ---- prologue: buffer 0
    {
#pragma unroll
        for (int r = 0; r < 2; r++) {
            unsigned d0 = (unsigned)__cvta_generic_to_shared(&pAh[0][(arow + 64 * r) * SA_STR + acol]);
            unsigned d1 = (unsigned)__cvta_generic_to_shared(&pAl[0][(arow + 64 * r) * SA_STR + acol]);
            CP_ASYNC16(d0, &Ah[(long)(m0 + arow + 64 * r) * K + acol]);
            CP_ASYNC16(d1, &Al[(long)(m0 + arow + 64 * r) * K + acol]);
        }
        CP_COMMIT();
#pragma unroll
        for (int j = 0; j < 2; j++) {
            const unsigned* src = &Bp[(long)bR[j] * N + n0 + bC[j]];
            stB[2 * j]     = *(const uint4*)src;
            stB[2 * j + 1] = *(const uint4*)(src + 4);
        }
#pragma unroll
        for (int j = 0; j < 2; j++) {
            uint4 u0 = stB[2 * j], u1 = stB[2 * j + 1];
            uint4 hv = make_uint4(__byte_perm(u0.x, u0.y, 0x5410), __byte_perm(u0.z, u0.w, 0x5410),
                                  __byte_perm(u1.x, u1.y, 0x5410), __byte_perm(u1.z, u1.w, 0x5410));
            uint4 lv = make_uint4(__byte_perm(u0.x, u0.y, 0x7632), __byte_perm(u0.z, u0.w, 0x7632),
                                  __byte_perm(u1.x, u1.y, 0x7632), __byte_perm(u1.z, u1.w, 0x7632));
            *(uint4*)&pBh[0][bR[j] * SB_STR + bC[j]] = hv;
            *(uint4*)&pBl[0][bR[j] * SB_STR + bC[j]] = lv;
        }
        CP_WAIT0();
        __syncthreads();
    }

    for (int i = 0; i < nk; i++) {
        int cur = i & 1, nxt = cur ^ 1;
        bool has_next = (i + 1 < nk);
        if (has_next) {
            int k0 = (i + 1) * BK;
#pragma unroll
            for (int r = 0; r < 2; r++) {
                unsigned d0 = (unsigned)__cvta_generic_to_shared(&pAh[nxt][(arow + 64 * r) * SA_STR + acol]);
                unsigned d1 = (unsigned)__cvta_generic_to_shared(&pAl[nxt][(arow + 64 * r) * SA_STR + acol]);
                CP_ASYNC16(d0, &Ah[(long)(m0 + arow + 64 * r) * K + k0 + acol]);
                CP_ASYNC16(d1, &Al[(long)(m0 + arow + 64 * r) * K + k0 + acol]);
            }
            CP_COMMIT();
#pragma unroll
            for (int j = 0; j < 2; j++) {
                const unsigned* src = &Bp[(long)(k0 + bR[j]) * N + n0 + bC[j]];
                stB[2 * j]     = *(const uint4*)src;
                stB[2 * j + 1] = *(const uint4*)(src + 4);
            }
        }

        // compute buffer cur
#pragma unroll
        for (int kk = 0; kk < BK; kk += 16) {
            unsigned ah[4][4], al[4][4], bh4[2][4], bl4[2][4];
#pragma unroll
            for (int mi = 0; mi < 4; mi++) {
                LDSM_X4(ah[mi], &pAh[cur][(wm * 64 + mi * 16 + lr) * SA_STR + kk + lc]);
                LDSM_X4(al[mi], &pAl[cur][(wm * 64 + mi * 16 + lr) * SA_STR + kk + lc]);
            }
#pragma unroll
            for (int ni2 = 0; ni2 < 2; ni2++) {
                LDSM_X4T(bh4[ni2], &pBh[cur][(kk + brow2) * SB_STR + wn * 32 + ni2 * 16 + bcol2]);
                LDSM_X4T(bl4[ni2], &pBl[cur][(kk + brow2) * SB_STR + wn * 32 + ni2 * 16 + bcol2]);
            }
#pragma unroll
            for (int mi = 0; mi < 4; mi++)
#pragma unroll
                for (int ni = 0; ni < 4; ni++) {
                    unsigned* bh = bh4[ni >> 1] + (ni & 1) * 2;
                    unsigned* bl = bl4[ni >> 1] + (ni & 1) * 2;
                    MMA_BF16(acc[mi][ni], ah[mi], bh);
                    MMA_BF16(acc[mi][ni], ah[mi], bl);
                    MMA_BF16(acc[mi][ni], al[mi], bh);
                }
        }

        if (has_next) {
#pragma unroll
            for (int j = 0; j < 2; j++) {
                uint4 u0 = stB[2 * j], u1 = stB[2 * j + 1];
                uint4 hv = make_uint4(__byte_perm(u0.x, u0.y, 0x5410), __byte_perm(u0.z, u0.w, 0x5410),
                                      __byte_perm(u1.x, u1.y, 0x5410), __byte_perm(u1.z, u1.w, 0x5410));
                uint4 lv = make_uint4(__byte_perm(u0.x, u0.y, 0x7632), __byte_perm(u0.z, u0.w, 0x7632),
                                      __byte_perm(u1.x, u1.y, 0x7632), __byte_perm(u1.z, u1.w, 0x7632));
                *(uint4*)&pBh[nxt][bR[j] * SB_STR + bC[j]] = hv;
                *(uint4*)&pBl[nxt][bR[j] * SB_STR + bC[j]] = lv;
            }
            CP_WAIT0();
        }
        __syncthreads();
    }

    int r = lane >> 2, cc = (lane & 3) * 2;
    if (mode == 2) {
        const float* bias = s ? bias1 : bias0;
#pragma unroll
        for (int mi = 0; mi < 4; mi++)
#pragma unroll
            for (int ni = 0; ni < 4; ni++)
#pragma unroll
                for (int half = 0; half < 2; half++) {
                    int m = m0 + wm * 64 + mi * 16 + r + half * 8;
                    int n = n0 + wn * 32 + ni * 8 + cc;
                    float bv = bias[m];
                    float2 v = make_float2(acc[mi][ni][half * 2] + bv,
                                           acc[mi][ni][half * 2 + 1] + bv);
                    *(float2*)&Ob[((long)z * M + m) * N + n] = v;
                }
    } else {
#pragma unroll
        for (int mi = 0; mi < 4; mi++)
#pragma unroll
            for (int ni = 0; ni < 4; ni++)
#pragma unroll
                for (int half = 0; half < 2; half++) {
                    int ml = wm * 64 + mi * 16 + r + half * 8;
                    int nl = wn * 32 + ni * 8 + cc;
                    sC[ml * 129 + nl]     = pack_pair(acc[mi][ni][half * 2]);
                    sC[ml * 129 + nl + 1] = pack_pair(acc[mi][ni][half * 2 + 1]);
                }
        __syncthreads();

        int n = tid & 127, hh = tid >> 7;
        int mrow = m0 + hh * 64;
        unsigned* dst;
        long base;
        if (mode == 0) {
            dst = g_q;
            base = ((long)(z * 8 + (mrow >> 6)) * 1024 + n0 + n) * 64;
        } else if (mrow < 512) {
            dst = g_k;
            base = ((long)(z * 8 + (mrow >> 6)) * 256 + n0 + n) * 64;
        } else {
            dst = g_v;
            base = ((long)(z * 8 + ((mrow - 512) >> 6)) * 256 + n0 + n) * 64;
        }
#pragma unroll
        for (int d4 = 0; d4 < 64; d4 += 4) {
            uint4 t;
            t.x = sC[(hh * 64 + d4 + 0) * 129 + n];
            t.y = sC[(hh * 64 + d4 + 1) * 129 + n];
            t.z = sC[(hh * 64 + d4 + 2) * 129 + n];
            t.w = sC[(hh * 64 + d4 + 3) * 129 + n];
            *(uint4*)&dst[base + d4] = t;
        }
    }
}

// ---------------------------------------------------------------------------
// Tensorized cross attention (unchanged from R9; x4-paired ldmatrix).
// ---------------------------------------------------------------------------
#define ATT_SMEM 184320

__global__ __launch_bounds__(256) void attn_kernel()
{
    extern __shared__ char smx[];
    __nv_bfloat16* Kh = (__nv_bfloat16*)(smx);
    __nv_bfloat16* Kl = (__nv_bfloat16*)(smx + 36864);
    __nv_bfloat16* Vh = (__nv_bfloat16*)(smx + 73728);
    __nv_bfloat16* Vl = (__nv_bfloat16*)(smx + 110592);
    __nv_bfloat16* Qh = (__nv_bfloat16*)(smx + 147456);
    __nv_bfloat16* Ql = (__nv_bfloat16*)(smx + 165888);
    float*        Ost = (float*)(smx + 147456);

    int bid = blockIdx.x;
    int qt = bid & 7, bhs = bid >> 3;
    int s = bhs >> 7, bh = bhs & 127, h = bh & 7, b = bh >> 3;

    const unsigned* qp = g_q + ((long)(s * 128 + bh) * 1024 + qt * 128) * 64;
    const unsigned* kp = g_k + (long)((1 - s) * 128 + bh) * 256 * 64;
    const unsigned* vp = g_v + (long)((1 - s) * 128 + bh) * 256 * 64;

    int tid = threadIdx.x, lane = tid & 31, w = tid >> 5;

    for (int c = tid; c < 4096; c += 256) {
        int row = c >> 4, seg = (c & 15) * 4;
        uint4 u = *(const uint4*)&kp[row * 64 + seg];
        *(uint2*)&Kh[row * 72 + seg] = make_uint2(__byte_perm(u.x, u.y, 0x5410), __byte_perm(u.z, u.w, 0x5410));
        *(uint2*)&Kl[row * 72 + seg] = make_uint2(__byte_perm(u.x, u.y, 0x7632), __byte_perm(u.z, u.w, 0x7632));
        u = *(const uint4*)&vp[row * 64 + seg];
        *(uint2*)&Vh[row * 72 + seg] = make_uint2(__byte_perm(u.x, u.y, 0x5410), __byte_perm(u.z, u.w, 0x5410));
        *(uint2*)&Vl[row * 72 + seg] = make_uint2(__byte_perm(u.x, u.y, 0x7632), __byte_perm(u.z, u.w, 0x7632));
    }
    for (int c = tid; c < 2048; c += 256) {
        int row = c >> 4, seg = (c & 15) * 4;
        uint4 u = *(const uint4*)&qp[row * 64 + seg];
        *(uint2*)&Qh[row * 72 + seg] = make_uint2(__byte_perm(u.x, u.y, 0x5410), __byte_perm(u.z, u.w, 0x5410));
        *(uint2*)&Ql[row * 72 + seg] = make_uint2(__byte_perm(u.x, u.y, 0x7632), __byte_perm(u.z, u.w, 0x7632));
    }
    __syncthreads();

    float sreg[32][4];
#pragma unroll
    for (int nt = 0; nt < 32; nt++) {
        sreg[nt][0] = 0.f; sreg[nt][1] = 0.f; sreg[nt][2] = 0.f; sreg[nt][3] = 0.f;
    }
    int r0 = w * 16;
    int krow = (lane & 7) + ((lane >> 4) << 3);
    for (int kk = 0; kk < 4; kk++) {
        unsigned ah[4], al[4];
        int qoff = (r0 + (lane & 15)) * 72 + kk * 16 + (lane >> 4) * 8;
        LDSM_X4(ah, &Qh[qoff]);
        LDSM_X4(al, &Ql[qoff]);
        int koff = kk * 16 + ((lane >> 3) & 1) * 8;
#pragma unroll
        for (int nt2 = 0; nt2 < 16; nt2++) {
            unsigned kh4[4], kl4[4];
            LDSM_X4(kh4, &Kh[(nt2 * 16 + krow) * 72 + koff]);
            LDSM_X4(kl4, &Kl[(nt2 * 16 + krow) * 72 + koff]);
            MMA_BF16(sreg[2 * nt2],     ah, (kh4 + 0));
            MMA_BF16(sreg[2 * nt2],     ah, (kl4 + 0));
            MMA_BF16(sreg[2 * nt2],     al, (kh4 + 0));
            MMA_BF16(sreg[2 * nt2 + 1], ah, (kh4 + 2));
            MMA_BF16(sreg[2 * nt2 + 1], ah, (kl4 + 2));
            MMA_BF16(sreg[2 * nt2 + 1], al, (kh4 + 2));
        }
    }

    float inv0, inv1;
    {
        float m0 = -1e30f, m1 = -1e30f;
#pragma unroll
        for (int nt = 0; nt < 32; nt++) {
            m0 = fmaxf(m0, fmaxf(sreg[nt][0], sreg[nt][1]));
            m1 = fmaxf(m1, fmaxf(sreg[nt][2], sreg[nt][3]));
        }
        m0 = fmaxf(m0, __shfl_xor_sync(0xffffffffu, m0, 1));
        m0 = fmaxf(m0, __shfl_xor_sync(0xffffffffu, m0, 2));
        m1 = fmaxf(m1, __shfl_xor_sync(0xffffffffu, m1, 1));
        m1 = fmaxf(m1, __shfl_xor_sync(0xffffffffu, m1, 2));
        float s0 = 0.f, s1 = 0.f;
#pragma unroll
        for (int nt = 0; nt < 32; nt++) {
            float e0 = __expf(sreg[nt][0] - m0); sreg[nt][0] = e0; s0 += e0;
            float e1 = __expf(sreg[nt][1] - m0); sreg[nt][1] = e1; s0 += e1;
            float e2 = __expf(sreg[nt][2] - m1); sreg[nt][2] = e2; s1 += e2;
            float e3 = __expf(sreg[nt][3] - m1); sreg[nt][3] = e3; s1 += e3;
        }
        s0 += __shfl_xor_sync(0xffffffffu, s0, 1);
        s0 += __shfl_xor_sync(0xffffffffu, s0, 2);
        s1 += __shfl_xor_sync(0xffffffffu, s1, 1);
        s1 += __shfl_xor_sync(0xffffffffu, s1, 2);
        inv0 = 1.f / s0;
        inv1 = 1.f / s1;
    }

    float oreg[8][4] = {};
#pragma unroll
    for (int kt = 0; kt < 16; kt++) {
        unsigned pah[4], pal[4];
        pack2(sreg[2 * kt][0],     sreg[2 * kt][1],     pah[0], pal[0]);
        pack2(sreg[2 * kt][2],     sreg[2 * kt][3],     pah[1], pal[1]);
        pack2(sreg[2 * kt + 1][0], sreg[2 * kt + 1][1], pah[2], pal[2]);
        pack2(sreg[2 * kt + 1][2], sreg[2 * kt + 1][3], pah[3], pal[3]);
        int vrow = kt * 16 + (lane & 7) + ((lane >> 3) & 1) * 8;
        int vcol = (lane >> 4) << 3;
#pragma unroll
        for (int nd2 = 0; nd2 < 4; nd2++) {
            unsigned vh4[4], vl4[4];
            LDSM_X4T(vh4, &Vh[vrow * 72 + nd2 * 16 + vcol]);
            LDSM_X4T(vl4, &Vl[vrow * 72 + nd2 * 16 + vcol]);
            MMA_BF16(oreg[2 * nd2],     pah, (vh4 + 0));
            MMA_BF16(oreg[2 * nd2],     pah, (vl4 + 0));
            MMA_BF16(oreg[2 * nd2],     pal, (vh4 + 0));
            MMA_BF16(oreg[2 * nd2 + 1], pah, (vh4 + 2));
            MMA_BF16(oreg[2 * nd2 + 1], pah, (vl4 + 2));
            MMA_BF16(oreg[2 * nd2 + 1], pal, (vh4 + 2));
        }
    }

    __syncthreads();
    int r = lane >> 2, cc = (lane & 3) * 2;
#pragma unroll
    for (int nd = 0; nd < 8; nd++) {
        Ost[(r0 + r) * 65 + nd * 8 + cc]         = oreg[nd][0] * inv0;
        Ost[(r0 + r) * 65 + nd * 8 + cc + 1]     = oreg[nd][1] * inv0;
        Ost[(r0 + r + 8) * 65 + nd * 8 + cc]     = oreg[nd][2] * inv1;
        Ost[(r0 + r + 8) * 65 + nd * 8 + cc + 1] = oreg[nd][3] * inv1;
    }
    __syncthreads();

    unsigned* op = g_o + ((long)(s * 16 + b) * 512 + h * 64) * 1024 + qt * 128;
    int plane = lane * 4;
    for (int dd = w; dd < 64; dd += 8) {
        uint4 t;
        t.x = pack_pair(Ost[(plane + 0) * 65 + dd]);
        t.y = pack_pair(Ost[(plane + 1) * 65 + dd]);
        t.z = pack_pair(Ost[(plane + 2) * 65 + dd]);
        t.w = pack_pair(Ost[(plane + 3) * 65 + dd]);
        *(uint4*)&op[(long)dd * 1024 + plane] = t;
    }
}

// ---------------------------------------------------------------------------
// Orchestration (attn stays at launch index 5 for the fixed ncu window).
// ---------------------------------------------------------------------------
extern "C" void kernel_launch(void* const* d_in, const int* in_sizes, int n_in,
                              void* d_out, int out_size)
{
    (void)in_sizes; (void)n_in; (void)out_size;
    #define F(i) ((const float*)d_in[i])

    cudaFuncSetAttribute(mma_gemm, cudaFuncAttributeMaxDynamicSharedMemorySize, GEMM_SMEM);
    cudaFuncSetAttribute(attn_kernel, cudaFuncAttributeMaxDynamicSharedMemorySize, ATT_SMEM);

    // 0: weight splits
    split_all_kernel<<<4096, 256>>>(F(7), F(19), F(13), F(25), F(26), F(28));

    // 1-2: depthwise convs
    int tot1 = 16 * 256 * 1024;
    int tot2 = 16 * 256 * 256;
    dwconv2_kernel<<<dim3((tot1 + 255) / 256, 2), 256>>>(
        F(0), F(1), F(2), F(3), F(4), F(5), F(6),
        F(14), F(15), F(16), F(17), F(18), 0, 1, 32);
    dwconv2_kernel<<<dim3((tot2 + 255) / 256, 2), 256>>>(
        F(0), F(1), F(8), F(9), F(10), F(11), F(12),
        F(20), F(21), F(22), F(23), F(24), 1, 2, 16);

    // 3: q projection  [512,1024]
    mma_gemm<<<dim3(1024 / BN, 512 / BM, 32), 256, GEMM_SMEM>>>(512, 1024, 256, 0, nullptr, nullptr, nullptr);
    // 4: kv projection [1024,256]
    mma_gemm<<<dim3(256 / BN, 1024 / BM, 32), 256, GEMM_SMEM>>>(1024, 256, 256, 1, nullptr, nullptr, nullptr);

    // 5: attention
    attn_kernel<<<2048, 256, ATT_SMEM>>>();

    // 6: out projection [256,1024]
    mma_gemm<<<dim3(1024 / BN, 256 / BM, 32), 256, GEMM_SMEM>>>(256, 1024, 512, 2, (float*)d_out, F(27), F(29));

    #undef F
}